// round 14
// baseline (speedup 1.0000x reference)
#include <cuda_runtime.h>
#include <cuda_bf16.h>
#include <cstdint>

// ---------------------------------------------------------------------------
// EfficientViT block. HMMA mma.sync bf16 hi/lo-split GEMMs, blocked bf16
// images as the only activation storage, cp.async.bulk mainloop, smem-tiled
// dws, register-resident per-row attention (broadcast smem reads).
// ---------------------------------------------------------------------------

#define TOK   50176

__device__ float g_qkv[TOK * 384];
__device__ float g_q2[TOK * 64];

// blocked hi/lo bf16 images: [128 rows x 32 k] tiles, stride 40, hi+lo = 20480B
__device__ __align__(16) unsigned char g_xAs[TOK * 256 * 5];
__device__ __align__(16) unsigned char g_hs [TOK * 512 * 5];
__device__ __align__(16) unsigned char g_obs[TOK * 256 * 5];
__device__ __align__(16) unsigned char g_xBs[TOK * 256 * 5];
__device__ __align__(16) unsigned char g_wtB[3440640];

#define WB_F0W1 0
#define WB_F0W2 655360
#define WB_QKV  1310720
#define WB_PROJ 1802240
#define WB_F1W1 2129920
#define WB_F1W2 2785280

__device__ __forceinline__ uint32_t smem_u32(const void* p) {
    uint32_t a;
    asm("{ .reg .u64 t; cvta.to.shared.u64 t, %1; cvt.u32.u64 %0, t; }"
        : "=r"(a) : "l"(p));
    return a;
}
__device__ __forceinline__ void ldsm4(uint32_t* r, uint32_t addr) {
    asm volatile("ldmatrix.sync.aligned.m8n8.x4.shared.b16 {%0,%1,%2,%3}, [%4];"
        : "=r"(r[0]), "=r"(r[1]), "=r"(r[2]), "=r"(r[3]) : "r"(addr));
}
__device__ __forceinline__ void mma16816(float* c, const uint32_t* a,
                                         const uint32_t* b) {
    asm volatile(
        "mma.sync.aligned.m16n8k16.row.col.f32.bf16.bf16.f32 "
        "{%0,%1,%2,%3}, {%4,%5,%6,%7}, {%8,%9}, {%0,%1,%2,%3};"
        : "+f"(c[0]), "+f"(c[1]), "+f"(c[2]), "+f"(c[3])
        : "r"(a[0]), "r"(a[1]), "r"(a[2]), "r"(a[3]), "r"(b[0]), "r"(b[1]));
}

// packed f32x2 FMA
__device__ __forceinline__ unsigned long long pack2f(float lo, float hi) {
    unsigned long long r;
    asm("mov.b64 %0, {%1,%2};" : "=l"(r) : "f"(lo), "f"(hi));
    return r;
}
__device__ __forceinline__ void ffma2(unsigned long long& d,
                                      unsigned long long a,
                                      unsigned long long b) {
    asm("fma.rn.f32x2 %0, %1, %2, %3;" : "=l"(d) : "l"(a), "l"(b), "l"(d));
}
__device__ __forceinline__ float2 unpack2f(unsigned long long v) {
    float2 f;
    asm("mov.b64 {%0,%1}, %2;" : "=f"(f.x), "=f"(f.y) : "l"(v));
    return f;
}

#define MBARRIER_INIT(mbar_addr, count) \
    asm volatile("mbarrier.init.shared.b64 [%0], %1;" \
        :: "r"((uint32_t)(mbar_addr)), "r"((uint32_t)(count)) : "memory")
#define MBARRIER_EXPECT_TX(mbar_addr, tx_bytes) \
    asm volatile("mbarrier.arrive.expect_tx.shared.b64 _, [%0], %1;" \
        :: "r"((uint32_t)(mbar_addr)), "r"((uint32_t)(tx_bytes)) : "memory")
#define MBARRIER_WAIT_PARITY(mbar_addr, parity) do { \
    uint32_t _mbar = (uint32_t)(mbar_addr); \
    uint32_t _par = (uint32_t)(parity); \
    uint32_t _done; \
    asm volatile( \
        "{\n\t.reg .pred p;\n\t" \
        "mbarrier.try_wait.parity.acquire.cta.shared::cta.b64 p, [%1], %2;\n\t" \
        "selp.b32 %0, 1, 0, p;\n\t}" \
        : "=r"(_done) : "r"(_mbar), "r"(_par) : "memory"); \
    if (!_done) { \
        asm volatile( \
            "{\n\t.reg .pred P1;\n\t" \
            "WAIT_LOOP_%=:\n\t" \
            "mbarrier.try_wait.parity.acquire.cta.shared::cta.b64 P1, [%0], %1, 0x989680;\n\t" \
            "@P1 bra.uni WAIT_DONE_%=;\n\t" \
            "bra.uni WAIT_LOOP_%=;\n\t" \
            "WAIT_DONE_%=:\n\t}" \
            :: "r"(_mbar), "r"(_par) : "memory"); \
    } \
} while (0)

__device__ __forceinline__ void bulkcp(uint32_t dst, const void* src,
                                       uint32_t mbar) {
    asm volatile(
        "cp.async.bulk.shared::cta.global.mbarrier::complete_tx::bytes "
        "[%0], [%1], %2, [%3];"
        :: "r"(dst), "l"(src), "r"(20480u), "r"(mbar) : "memory");
}

// blocked-image byte offset of (row, col) hi element; lo at +10240
__device__ __forceinline__ long img_off(long row, int col, int Kd) {
    return ((row >> 7) * (Kd >> 5) + (col >> 5)) * 20480L +
           (row & 127) * 80 + (col & 31) * 2;
}
__device__ __forceinline__ float img_read(const unsigned char* img, long row,
                                          int col, int Kd) {
    long off = img_off(row, col, Kd);
    return __bfloat162float(*(const __nv_bfloat16*)(img + off)) +
           __bfloat162float(*(const __nv_bfloat16*)(img + off + 10240));
}

#define TS 40
__device__ __forceinline__ uint32_t a_addr(uint32_t base, int m, int k, int lane) {
    int g = lane >> 3, r = lane & 7;
    return base + ((m + ((g & 1) << 3) + r) * TS + k + ((g >> 1) << 3)) * 2;
}
__device__ __forceinline__ uint32_t b_addr(uint32_t base, int n, int k, int lane) {
    int g = lane >> 3, r = lane & 7;
    return base + ((n + ((g >> 1) << 3) + r) * TS + k + ((g & 1) << 3)) * 2;
}

__device__ __forceinline__ void split_bf16(float v, __nv_bfloat16& h,
                                           __nv_bfloat16& l) {
    h = __float2bfloat16(v);
    l = __float2bfloat16(v - __bfloat162float(h));
}
__device__ __forceinline__ void img_write(unsigned char* img, long row, int col,
                                          int Kd, float v0, float v1) {
    __nv_bfloat16 h0, l0, h1, l1;
    split_bf16(v0, h0, l0);
    split_bf16(v1, h1, l1);
    long off = img_off(row, col, Kd);
    __nv_bfloat162 hv, lv;
    hv.x = h0; hv.y = h1;
    lv.x = l0; lv.y = l1;
    *(__nv_bfloat162*)(img + off) = hv;
    *(__nv_bfloat162*)(img + off + 10240) = lv;
}

// ---------------------------------------------------------------------------
// All-weights split into blocked images, one launch
// ---------------------------------------------------------------------------
__global__ void wconv_all(const float* __restrict__ w0, const float* __restrict__ w1,
                          const float* __restrict__ w2, const float* __restrict__ w3,
                          const float* __restrict__ w4, const float* __restrict__ w5,
                          unsigned char* __restrict__ dst) {
    long i = (long)blockIdx.x * 256 + threadIdx.x;
    if (i >= 688128) return;
    const long cum[7] = {0, 131072, 262144, 360448, 425984, 557056, 688128};
    const long ob[6] = {WB_F0W1, WB_F0W2, WB_QKV, WB_PROJ, WB_F1W1, WB_F1W2};
    const int Ks[6] = {256, 512, 256, 256, 256, 512};
    const float* srcs[6] = {w0, w1, w2, w3, w4, w5};
    int s = 0;
    while (i >= cum[s + 1]) s++;
    long j = i - cum[s];
    int K = Ks[s];
    long n = j / K;
    int k = (int)(j % K);
    __nv_bfloat16 h, l;
    split_bf16(srcs[s][j], h, l);
    long off = ob[s] + img_off(n, k, K);
    *(__nv_bfloat16*)(dst + off) = h;
    *(__nv_bfloat16*)(dst + off + 10240) = l;
}

// ---------------------------------------------------------------------------
// HMMA GEMM. epi: 0 fp32 out ; 1 relu->img ; 2 resid(img)+ ->img
//             3 resid(img)+ -> NCHW fp32 transpose out
// ---------------------------------------------------------------------------
__global__ void __launch_bounds__(256, 2) mm_gemm(
    const unsigned char* __restrict__ Aimg, const unsigned char* __restrict__ Bimg,
    const float* __restrict__ sc, const float* __restrict__ bi,
    const unsigned char* __restrict__ residImg, float* __restrict__ Cf,
    unsigned char* __restrict__ Chl,
    int N, int K, int epi)
{
    extern __shared__ __align__(128) unsigned char dsm[];
    __shared__ __align__(8) unsigned long long mbars[2];
    int tid = threadIdx.x, lane = tid & 31, wid = tid >> 5;
    int wm = (wid & 1) << 6, wn = (wid >> 1) << 5;
    long bm = (long)blockIdx.y << 7;
    int bn = blockIdx.x << 7;
    int KT = K >> 5;

    float acc[4][4][4] = {};
    uint32_t sbase = smem_u32(dsm);
    uint32_t mb = smem_u32(mbars);

    if (tid == 0) {
        MBARRIER_INIT(mb, 1);
        MBARRIER_INIT(mb + 8, 1);
    }
    __syncthreads();

    const unsigned char* Ab = Aimg + (long)blockIdx.y * KT * 20480;
    const unsigned char* Bb = Bimg + (long)blockIdx.x * KT * 20480;

    if (tid == 0) {
        MBARRIER_EXPECT_TX(mb, 40960);
        bulkcp(sbase, Ab, mb);
        bulkcp(sbase + 20480, Bb, mb);
        if (KT > 1) {
            MBARRIER_EXPECT_TX(mb + 8, 40960);
            bulkcp(sbase + 40960, Ab + 20480, mb + 8);
            bulkcp(sbase + 61440, Bb + 20480, mb + 8);
        }
    }

    for (int t = 0; t < KT; t++) {
        MBARRIER_WAIT_PARITY(mb + (t & 1) * 8, (t >> 1) & 1);
        uint32_t sAh = sbase + (t & 1) * 40960;
        uint32_t sAl = sAh + 10240;
        uint32_t sBh = sAh + 20480;
        uint32_t sBl = sAh + 30720;
#pragma unroll
        for (int kk = 0; kk < 32; kk += 16) {
            uint32_t ah[4][4], al[4][4], bh[2][4], bl[2][4];
#pragma unroll
            for (int mt = 0; mt < 4; mt++)
                ldsm4(ah[mt], a_addr(sAh, wm + mt * 16, kk, lane));
#pragma unroll
            for (int h = 0; h < 2; h++)
                ldsm4(bh[h], b_addr(sBh, wn + h * 16, kk, lane));
#pragma unroll
            for (int mt = 0; mt < 4; mt++)
#pragma unroll
                for (int nt = 0; nt < 4; nt++)
                    mma16816(acc[mt][nt], ah[mt], &bh[nt >> 1][(nt & 1) * 2]);
#pragma unroll
            for (int h = 0; h < 2; h++)
                ldsm4(bl[h], b_addr(sBl, wn + h * 16, kk, lane));
#pragma unroll
            for (int mt = 0; mt < 4; mt++)
#pragma unroll
                for (int nt = 0; nt < 4; nt++)
                    mma16816(acc[mt][nt], ah[mt], &bl[nt >> 1][(nt & 1) * 2]);
#pragma unroll
            for (int mt = 0; mt < 4; mt++)
                ldsm4(al[mt], a_addr(sAl, wm + mt * 16, kk, lane));
#pragma unroll
            for (int mt = 0; mt < 4; mt++)
#pragma unroll
                for (int nt = 0; nt < 4; nt++)
                    mma16816(acc[mt][nt], al[mt], &bh[nt >> 1][(nt & 1) * 2]);
        }
        __syncthreads();
        if (tid == 0 && t + 2 < KT) {
            uint32_t b8 = mb + (t & 1) * 8;
            uint32_t sb = sbase + (t & 1) * 40960;
            MBARRIER_EXPECT_TX(b8, 40960);
            bulkcp(sb, Ab + (long)(t + 2) * 20480, b8);
            bulkcp(sb + 20480, Bb + (long)(t + 2) * 20480, b8);
        }
    }

    int q = lane >> 2, tq = lane & 3;

    if (epi == 3) {
        float* tile = (float*)dsm;   // [128][129]
#pragma unroll
        for (int nt = 0; nt < 4; nt++) {
            int nl = wn + nt * 8 + tq * 2;
            int n = bn + nl;
            float2 s2 = *(const float2*)(sc + n);
            float2 b2 = *(const float2*)(bi + n);
#pragma unroll
            for (int mt = 0; mt < 4; mt++) {
#pragma unroll
                for (int half = 0; half < 2; half++) {
                    int row = wm + mt * 16 + q + half * 8;
                    long m = bm + row;
                    long off = img_off(m, n, N);
                    __nv_bfloat162 rh = *(const __nv_bfloat162*)(residImg + off);
                    __nv_bfloat162 rl = *(const __nv_bfloat162*)(residImg + off + 10240);
                    tile[row * 129 + nl]     = acc[mt][nt][half * 2 + 0] * s2.x + b2.x +
                        __bfloat162float(rh.x) + __bfloat162float(rl.x);
                    tile[row * 129 + nl + 1] = acc[mt][nt][half * 2 + 1] * s2.y + b2.y +
                        __bfloat162float(rh.y) + __bfloat162float(rl.y);
                }
            }
        }
        __syncthreads();
#pragma unroll
        for (int ci = 0; ci < 16; ci++) {
            int c = wid * 16 + ci;
#pragma unroll
            for (int rc = 0; rc < 4; rc++) {
                int row = rc * 32 + lane;
                long tk = bm + row;
                int b = (int)(tk / 784), tr = (int)(tk % 784);
                Cf[((long)(b * 256 + bn + c)) * 784 + tr] = tile[row * 129 + c];
            }
        }
        return;
    }

#pragma unroll
    for (int nt = 0; nt < 4; nt++) {
        int n = bn + wn + nt * 8 + tq * 2;
        float2 s2 = *(const float2*)(sc + n);
        float2 b2 = *(const float2*)(bi + n);
#pragma unroll
        for (int mt = 0; mt < 4; mt++) {
#pragma unroll
            for (int half = 0; half < 2; half++) {
                long m = bm + wm + mt * 16 + q + half * 8;
                float v0 = acc[mt][nt][half * 2 + 0] * s2.x + b2.x;
                float v1 = acc[mt][nt][half * 2 + 1] * s2.y + b2.y;
                if (epi == 1) {
                    v0 = fmaxf(v0, 0.f);
                    v1 = fmaxf(v1, 0.f);
                } else if (epi == 2) {
                    long off = img_off(m, n, N);
                    __nv_bfloat162 rh = *(const __nv_bfloat162*)(residImg + off);
                    __nv_bfloat162 rl = *(const __nv_bfloat162*)(residImg + off + 10240);
                    v0 += __bfloat162float(rh.x) + __bfloat162float(rl.x);
                    v1 += __bfloat162float(rh.y) + __bfloat162float(rl.y);
                }
                if (epi == 0) {
                    float2 o;
                    o.x = v0; o.y = v1;
                    *(float2*)(Cf + m * N + n) = o;
                } else {
                    img_write(Chl, m, n, N, v0, v1);
                }
            }
        }
    }
}

// ---------------------------------------------------------------------------
// dw0: NCHW input -> blocked image only, xA = x + bn(dw3x3(x))
// ---------------------------------------------------------------------------
__global__ void __launch_bounds__(256) dw0_kernel(
    const float* __restrict__ x, const float* __restrict__ w,
    const float* __restrict__ s, const float* __restrict__ bb)
{
    __shared__ float sx[3][64][29];
    __shared__ float wsm[64][9];
    __shared__ float ssm[64], bsm[64];
    int c0 = blockIdx.x * 64;
    int h = blockIdx.y;
    int b = blockIdx.z;
    int tid = threadIdx.x;

    for (int i = tid; i < 64 * 9; i += 256) {
        int c = i / 9, k = i % 9;
        wsm[c][k] = w[(c0 + c) * 9 + k];
    }
    if (tid < 64) { ssm[tid] = s[c0 + tid]; bsm[tid] = bb[c0 + tid]; }

    for (int i = tid; i < 3 * 64 * 28; i += 256) {
        int row = i / 1792;
        int rem = i % 1792;
        int c = rem / 28, ww = rem % 28;
        int hh = h - 1 + row;
        float v = 0.f;
        if (hh >= 0 && hh < 28)
            v = x[(((long)(b * 256 + c0 + c)) * 28 + hh) * 28 + ww];
        sx[row][c][ww] = v;
    }
    __syncthreads();

    for (int i = tid; i < 64 * 28; i += 256) {
        int cl = i & 63, ww = i >> 6;
        float acc = 0.f;
#pragma unroll
        for (int dy = 0; dy < 3; dy++)
#pragma unroll
            for (int dx = 0; dx < 3; dx++) {
                int w2 = ww + dx - 1;
                if (w2 >= 0 && w2 < 28)
                    acc += wsm[cl][dy * 3 + dx] * sx[dy][cl][w2];
            }
        long t = (long)(b * 28 + h) * 28 + ww;
        float v = sx[1][cl][ww] + ssm[cl] * acc + bsm[cl];
        __nv_bfloat16 hh2, ll2;
        split_bf16(v, hh2, ll2);
        long off = img_off(t, c0 + cl, 256);
        *(__nv_bfloat16*)(g_xAs + off) = hh2;
        *(__nv_bfloat16*)(g_xAs + off + 10240) = ll2;
    }
}

// ---------------------------------------------------------------------------
// dw1: xB = xA + bn(dw3x3(xA)) from/to blocked images
// ---------------------------------------------------------------------------
__global__ void __launch_bounds__(256) dw1_kernel(
    const float* __restrict__ w, const float* __restrict__ s,
    const float* __restrict__ bb)
{
    int t = blockIdx.x;
    int c = threadIdx.x;
    int b = t / 784, rem = t % 784, h = rem / 28, ww = rem % 28;
    float wr[9];
#pragma unroll
    for (int k = 0; k < 9; k++) wr[k] = w[c * 9 + k];
    float acc = 0.f, center = 0.f;
#pragma unroll
    for (int dy = 0; dy < 3; dy++) {
        int h2 = h + dy - 1;
        if (h2 < 0 || h2 >= 28) continue;
#pragma unroll
        for (int dx = 0; dx < 3; dx++) {
            int w2 = ww + dx - 1;
            if (w2 < 0 || w2 >= 28) continue;
            float v = img_read(g_xAs, (long)(b * 784 + h2 * 28 + w2), c, 256);
            acc += wr[dy * 3 + dx] * v;
            if (dy == 1 && dx == 1) center = v;
        }
    }
    float out = center + s[c] * acc + bb[c];
    __nv_bfloat16 hh, ll;
    split_bf16(out, hh, ll);
    long off = img_off(t, c, 256);
    *(__nv_bfloat16*)(g_xBs + off) = hh;
    *(__nv_bfloat16*)(g_xBs + off + 10240) = ll;
}

// ---------------------------------------------------------------------------
// dws: 5x5 depthwise conv, smem-tiled per (batch, head). grid (64, 4), 256 thr
// ---------------------------------------------------------------------------
__global__ void __launch_bounds__(256) dws_kernel(
    const float* __restrict__ w, const float* __restrict__ s,
    const float* __restrict__ bb)
{
    extern __shared__ float sx[];   // [784][17]
    int b = blockIdx.x, head = blockIdx.y;
    int tid = threadIdx.x;
    int kc = tid & 15, tg = tid >> 4;

    for (int i = tid; i < 784 * 16; i += 256) {
        int t = i >> 4, k2 = i & 15;
        sx[t * 17 + k2] = g_qkv[((long)(b * 784 + t)) * 384 + head * 96 + k2];
    }
    __syncthreads();

    int ch = head * 16 + kc;
    float wr[25];
#pragma unroll
    for (int k = 0; k < 25; k++) wr[k] = w[ch * 25 + k];
    float sv = s[ch], bv = bb[ch];

    for (int j = 0; j < 49; j++) {
        int t = tg + (j << 4);
        int h = t / 28, ww = t % 28;
        float acc = 0.f;
#pragma unroll
        for (int dy = 0; dy < 5; dy++) {
            int h2 = h + dy - 2;
            if (h2 < 0 || h2 >= 28) continue;
#pragma unroll
            for (int dx = 0; dx < 5; dx++) {
                int w2 = ww + dx - 2;
                if (w2 < 0 || w2 >= 28) continue;
                acc += wr[dy * 5 + dx] * sx[(h2 * 28 + w2) * 17 + kc];
            }
        }
        g_q2[((long)(b * 784 + t)) * 64 + ch] = sv * acc + bv;
    }
}

// ---------------------------------------------------------------------------
// per-window attention. 128 threads load K/V to smem; 98 threads own
// (q-row, d-half): scores+softmax fully in registers, sv via broadcast LDS.128
// ---------------------------------------------------------------------------
__global__ void __launch_bounds__(128) attn_kernel(const float* __restrict__ pos)
{
    int wi = blockIdx.x >> 2, wj = blockIdx.x & 3;
    int head = blockIdx.y, b = blockIdx.z;
    int tid = threadIdx.x;

    __shared__ __align__(16) float sk[49 * 16];
    __shared__ __align__(16) float sv[49 * 64];
    __shared__ int stok[49];

    if (tid < 49)
        stok[tid] = b * 784 + (wi * 7 + tid / 7) * 28 + wj * 7 + (tid % 7);
    __syncthreads();

    for (int i = tid; i < 49 * 16; i += 128) {
        int r = i >> 4, c = i & 15;
        sk[i] = g_qkv[(long)stok[r] * 384 + head * 96 + 16 + c];
    }
    for (int i = tid; i < 49 * 64; i += 128) {
        int r = i >> 6, c = i & 63;
        sv[i] = g_qkv[(long)stok[r] * 384 + head * 96 + 32 + c];
    }
    __syncthreads();

    int qr = tid >> 1, dh = tid & 1;
    if (qr >= 49) return;
    long t = stok[qr];

    // q row -> registers
    float qv[16];
    {
        const float4* qp = (const float4*)&g_q2[t * 64 + head * 16];
#pragma unroll
        for (int j = 0; j < 4; j++) {
            float4 v = qp[j];
            qv[j * 4 + 0] = v.x;
            qv[j * 4 + 1] = v.y;
            qv[j * 4 + 2] = v.z;
            qv[j * 4 + 3] = v.w;
        }
    }

    // scores (registers), max
    const float* pe = pos + head * 2401 + qr * 49;
    float s[49];
    float mx = -1e30f;
#pragma unroll
    for (int kr = 0; kr < 49; kr++) {
        unsigned long long d2 = pack2f(0.f, 0.f);
        const unsigned long long* kp = (const unsigned long long*)&sk[kr * 16];
#pragma unroll
        for (int cc = 0; cc < 8; cc++)
            ffma2(d2, pack2f(qv[cc * 2], qv[cc * 2 + 1]), kp[cc]);
        float2 f = unpack2f(d2);
        float val = (f.x + f.y) * 0.25f + pe[kr];
        s[kr] = val;
        mx = fmaxf(mx, val);
    }
    // softmax in registers
    float sum = 0.f;
#pragma unroll
    for (int kr = 0; kr < 49; kr++) {
        float e = __expf(s[kr] - mx);
        s[kr] = e;
        sum += e;
    }
    float inv = 1.f / sum;

    // AV: this thread owns 32 d-values (dh half)
    unsigned long long out2[16];
#pragma unroll
    for (int j = 0; j < 16; j++) out2[j] = pack2f(0.f, 0.f);
    const unsigned long long* vbase =
        (const unsigned long long*)&sv[dh * 32];
#pragma unroll
    for (int k = 0; k < 49; k++) {
        unsigned long long p2 = pack2f(s[k], s[k]);
        const unsigned long long* vp = vbase + k * 32;
#pragma unroll
        for (int j = 0; j < 16; j++)
            ffma2(out2[j], p2, vp[j]);
    }

    int c0 = head * 64 + dh * 32;
#pragma unroll
    for (int j = 0; j < 16; j++) {
        float2 f = unpack2f(out2[j]);
        img_write(g_obs, t, c0 + j * 2, 256,
                  fmaxf(f.x * inv, 0.f), fmaxf(f.y * inv, 0.f));
    }
}

// ---------------------------------------------------------------------------
extern "C" void kernel_launch(void* const* d_in, const int* in_sizes, int n_in,
                              void* d_out, int out_size)
{
    const float* in[32];
    for (int i = 0; i < n_in && i < 32; i++) in[i] = (const float*)d_in[i];

    int idw0, idw1, iffn0, iffn1, iqkv, idws, iproj, ipos;
    if (in_sizes[4] > 100000) { // reference-signature order
        idw0 = 1;  iffn0 = 4;  iqkv = 10; idws = 13; iproj = 16;
        ipos = 19; idw1 = 20;  iffn1 = 23;
    } else {                    // setup_inputs dict order
        idw0 = 1;  idw1 = 4;   iffn0 = 7;  iffn1 = 13;
        iqkv = 19; idws = 22;  iproj = 25; ipos = 28;
    }

    const float* x     = in[0];
    const float* dw0_w = in[idw0],  * dw0_s = in[idw0 + 1], * dw0_b = in[idw0 + 2];
    const float* dw1_w = in[idw1],  * dw1_s = in[idw1 + 1], * dw1_b = in[idw1 + 2];
    const float* f0w1 = in[iffn0],     * f0s1 = in[iffn0 + 1], * f0b1 = in[iffn0 + 2];
    const float* f0w2 = in[iffn0 + 3], * f0s2 = in[iffn0 + 4], * f0b2 = in[iffn0 + 5];
    const float* f1w1 = in[iffn1],     * f1s1 = in[iffn1 + 1], * f1b1 = in[iffn1 + 2];
    const float* f1w2 = in[iffn1 + 3], * f1s2 = in[iffn1 + 4], * f1b2 = in[iffn1 + 5];
    const float* qkv_w = in[iqkv],  * qkv_s = in[iqkv + 1],  * qkv_b = in[iqkv + 2];
    const float* dws_w = in[idws],  * dws_s = in[idws + 1],  * dws_b = in[idws + 2];
    const float* proj_w = in[iproj], * proj_s = in[iproj + 1], * proj_b = in[iproj + 2];
    const float* pos = in[ipos];

    float* pqkv;
    unsigned char *pxAs, *phs, *pobs, *pxBs, *pwtB;
    cudaGetSymbolAddress((void**)&pqkv, g_qkv);
    cudaGetSymbolAddress((void**)&pxAs, g_xAs);
    cudaGetSymbolAddress((void**)&phs,  g_hs);
    cudaGetSymbolAddress((void**)&pobs, g_obs);
    cudaGetSymbolAddress((void**)&pxBs, g_xBs);
    cudaGetSymbolAddress((void**)&pwtB, g_wtB);

    const int SMEM_GEMM = 81920;
    cudaFuncSetAttribute(mm_gemm, cudaFuncAttributeMaxDynamicSharedMemorySize,
                         SMEM_GEMM);
    const int SMEM_DWS = 784 * 17 * 4;
    cudaFuncSetAttribute(dws_kernel, cudaFuncAttributeMaxDynamicSharedMemorySize,
                         SMEM_DWS);

    wconv_all<<<(688128 + 255) / 256, 256>>>(f0w1, f0w2, qkv_w, proj_w, f1w1,
                                             f1w2, pwtB);

    // 1. xA = x + bn(dw3x3(x))  -> image
    dw0_kernel<<<dim3(4, 28, 64), 256>>>(x, dw0_w, dw0_s, dw0_b);

    // 2. ffn0 (h image; then in-place xA image += ffn)
    mm_gemm<<<dim3(4, 392), 256, SMEM_GEMM>>>(
        pxAs, pwtB + WB_F0W1, f0s1, f0b1, nullptr, nullptr, phs, 512, 256, 1);
    mm_gemm<<<dim3(2, 392), 256, SMEM_GEMM>>>(
        phs, pwtB + WB_F0W2, f0s2, f0b2, pxAs, nullptr, pxAs, 256, 512, 2);

    // 3. attention
    mm_gemm<<<dim3(3, 392), 256, SMEM_GEMM>>>(
        pxAs, pwtB + WB_QKV, qkv_s, qkv_b, nullptr, pqkv, nullptr, 384, 256, 0);
    dws_kernel<<<dim3(64, 4), 256, SMEM_DWS>>>(dws_w, dws_s, dws_b);
    attn_kernel<<<dim3(16, 4, 64), 128>>>(pos);
    mm_gemm<<<dim3(2, 392), 256, SMEM_GEMM>>>(
        pobs, pwtB + WB_PROJ, proj_s, proj_b, pxAs, nullptr, pxAs, 256, 256, 2);

    // 4. xB image = xA + bn(dw3x3(xA))
    dw1_kernel<<<TOK, 256>>>(dw1_w, dw1_s, dw1_b);

    // 5. ffn1: h image, then final GEMM -> NCHW d_out (epi=3, resid xB image)
    mm_gemm<<<dim3(4, 392), 256, SMEM_GEMM>>>(
        pxBs, pwtB + WB_F1W1, f1s1, f1b1, nullptr, nullptr, phs, 512, 256, 1);
    mm_gemm<<<dim3(2, 392), 256, SMEM_GEMM>>>(
        phs, pwtB + WB_F1W2, f1s2, f1b2, pxBs, (float*)d_out, nullptr,
        256, 512, 3);
}

// round 15
// speedup vs baseline: 1.0097x; 1.0097x over previous
#include <cuda_runtime.h>
#include <cuda_bf16.h>
#include <cstdint>

// ---------------------------------------------------------------------------
// EfficientViT block. HMMA mma.sync bf16 hi/lo-split GEMMs, blocked bf16
// images as the only activation storage, cp.async.bulk mainloop, smem-tiled
// dws + dw1, R13-style window attention.
// ---------------------------------------------------------------------------

#define TOK   50176

__device__ float g_qkv[TOK * 384];
__device__ float g_q2[TOK * 64];

// blocked hi/lo bf16 images: [128 rows x 32 k] tiles, stride 40, hi+lo = 20480B
__device__ __align__(16) unsigned char g_xAs[TOK * 256 * 5];
__device__ __align__(16) unsigned char g_hs [TOK * 512 * 5];
__device__ __align__(16) unsigned char g_obs[TOK * 256 * 5];
__device__ __align__(16) unsigned char g_xBs[TOK * 256 * 5];
__device__ __align__(16) unsigned char g_wtB[3440640];

#define WB_F0W1 0
#define WB_F0W2 655360
#define WB_QKV  1310720
#define WB_PROJ 1802240
#define WB_F1W1 2129920
#define WB_F1W2 2785280

__device__ __forceinline__ uint32_t smem_u32(const void* p) {
    uint32_t a;
    asm("{ .reg .u64 t; cvta.to.shared.u64 t, %1; cvt.u32.u64 %0, t; }"
        : "=r"(a) : "l"(p));
    return a;
}
__device__ __forceinline__ void ldsm4(uint32_t* r, uint32_t addr) {
    asm volatile("ldmatrix.sync.aligned.m8n8.x4.shared.b16 {%0,%1,%2,%3}, [%4];"
        : "=r"(r[0]), "=r"(r[1]), "=r"(r[2]), "=r"(r[3]) : "r"(addr));
}
__device__ __forceinline__ void mma16816(float* c, const uint32_t* a,
                                         const uint32_t* b) {
    asm volatile(
        "mma.sync.aligned.m16n8k16.row.col.f32.bf16.bf16.f32 "
        "{%0,%1,%2,%3}, {%4,%5,%6,%7}, {%8,%9}, {%0,%1,%2,%3};"
        : "+f"(c[0]), "+f"(c[1]), "+f"(c[2]), "+f"(c[3])
        : "r"(a[0]), "r"(a[1]), "r"(a[2]), "r"(a[3]), "r"(b[0]), "r"(b[1]));
}

// packed f32x2 FMA
__device__ __forceinline__ unsigned long long pack2f(float lo, float hi) {
    unsigned long long r;
    asm("mov.b64 %0, {%1,%2};" : "=l"(r) : "f"(lo), "f"(hi));
    return r;
}
__device__ __forceinline__ void ffma2(unsigned long long& d,
                                      unsigned long long a,
                                      unsigned long long b) {
    asm("fma.rn.f32x2 %0, %1, %2, %3;" : "=l"(d) : "l"(a), "l"(b), "l"(d));
}
__device__ __forceinline__ float2 unpack2f(unsigned long long v) {
    float2 f;
    asm("mov.b64 {%0,%1}, %2;" : "=f"(f.x), "=f"(f.y) : "l"(v));
    return f;
}

#define MBARRIER_INIT(mbar_addr, count) \
    asm volatile("mbarrier.init.shared.b64 [%0], %1;" \
        :: "r"((uint32_t)(mbar_addr)), "r"((uint32_t)(count)) : "memory")
#define MBARRIER_EXPECT_TX(mbar_addr, tx_bytes) \
    asm volatile("mbarrier.arrive.expect_tx.shared.b64 _, [%0], %1;" \
        :: "r"((uint32_t)(mbar_addr)), "r"((uint32_t)(tx_bytes)) : "memory")
#define MBARRIER_WAIT_PARITY(mbar_addr, parity) do { \
    uint32_t _mbar = (uint32_t)(mbar_addr); \
    uint32_t _par = (uint32_t)(parity); \
    uint32_t _done; \
    asm volatile( \
        "{\n\t.reg .pred p;\n\t" \
        "mbarrier.try_wait.parity.acquire.cta.shared::cta.b64 p, [%1], %2;\n\t" \
        "selp.b32 %0, 1, 0, p;\n\t}" \
        : "=r"(_done) : "r"(_mbar), "r"(_par) : "memory"); \
    if (!_done) { \
        asm volatile( \
            "{\n\t.reg .pred P1;\n\t" \
            "WAIT_LOOP_%=:\n\t" \
            "mbarrier.try_wait.parity.acquire.cta.shared::cta.b64 P1, [%0], %1, 0x989680;\n\t" \
            "@P1 bra.uni WAIT_DONE_%=;\n\t" \
            "bra.uni WAIT_LOOP_%=;\n\t" \
            "WAIT_DONE_%=:\n\t}" \
            :: "r"(_mbar), "r"(_par) : "memory"); \
    } \
} while (0)

__device__ __forceinline__ void bulkcp(uint32_t dst, const void* src,
                                       uint32_t mbar) {
    asm volatile(
        "cp.async.bulk.shared::cta.global.mbarrier::complete_tx::bytes "
        "[%0], [%1], %2, [%3];"
        :: "r"(dst), "l"(src), "r"(20480u), "r"(mbar) : "memory");
}

// blocked-image byte offset of (row, col) hi element; lo at +10240
__device__ __forceinline__ long img_off(long row, int col, int Kd) {
    return ((row >> 7) * (Kd >> 5) + (col >> 5)) * 20480L +
           (row & 127) * 80 + (col & 31) * 2;
}
__device__ __forceinline__ float img_read(const unsigned char* img, long row,
                                          int col, int Kd) {
    long off = img_off(row, col, Kd);
    return __bfloat162float(*(const __nv_bfloat16*)(img + off)) +
           __bfloat162float(*(const __nv_bfloat16*)(img + off + 10240));
}

#define TS 40
__device__ __forceinline__ uint32_t a_addr(uint32_t base, int m, int k, int lane) {
    int g = lane >> 3, r = lane & 7;
    return base + ((m + ((g & 1) << 3) + r) * TS + k + ((g >> 1) << 3)) * 2;
}
__device__ __forceinline__ uint32_t b_addr(uint32_t base, int n, int k, int lane) {
    int g = lane >> 3, r = lane & 7;
    return base + ((n + ((g >> 1) << 3) + r) * TS + k + ((g & 1) << 3)) * 2;
}

__device__ __forceinline__ void split_bf16(float v, __nv_bfloat16& h,
                                           __nv_bfloat16& l) {
    h = __float2bfloat16(v);
    l = __float2bfloat16(v - __bfloat162float(h));
}
__device__ __forceinline__ void img_write(unsigned char* img, long row, int col,
                                          int Kd, float v0, float v1) {
    __nv_bfloat16 h0, l0, h1, l1;
    split_bf16(v0, h0, l0);
    split_bf16(v1, h1, l1);
    long off = img_off(row, col, Kd);
    __nv_bfloat162 hv, lv;
    hv.x = h0; hv.y = h1;
    lv.x = l0; lv.y = l1;
    *(__nv_bfloat162*)(img + off) = hv;
    *(__nv_bfloat162*)(img + off + 10240) = lv;
}

// ---------------------------------------------------------------------------
// All-weights split into blocked images, one launch
// ---------------------------------------------------------------------------
__global__ void wconv_all(const float* __restrict__ w0, const float* __restrict__ w1,
                          const float* __restrict__ w2, const float* __restrict__ w3,
                          const float* __restrict__ w4, const float* __restrict__ w5,
                          unsigned char* __restrict__ dst) {
    long i = (long)blockIdx.x * 256 + threadIdx.x;
    if (i >= 688128) return;
    const long cum[7] = {0, 131072, 262144, 360448, 425984, 557056, 688128};
    const long ob[6] = {WB_F0W1, WB_F0W2, WB_QKV, WB_PROJ, WB_F1W1, WB_F1W2};
    const int Ks[6] = {256, 512, 256, 256, 256, 512};
    const float* srcs[6] = {w0, w1, w2, w3, w4, w5};
    int s = 0;
    while (i >= cum[s + 1]) s++;
    long j = i - cum[s];
    int K = Ks[s];
    long n = j / K;
    int k = (int)(j % K);
    __nv_bfloat16 h, l;
    split_bf16(srcs[s][j], h, l);
    long off = ob[s] + img_off(n, k, K);
    *(__nv_bfloat16*)(dst + off) = h;
    *(__nv_bfloat16*)(dst + off + 10240) = l;
}

// ---------------------------------------------------------------------------
// HMMA GEMM. epi: 0 fp32 out ; 1 relu->img ; 2 resid(img)+ ->img
//             3 resid(img)+ -> NCHW fp32 transpose out
// ---------------------------------------------------------------------------
__global__ void __launch_bounds__(256, 2) mm_gemm(
    const unsigned char* __restrict__ Aimg, const unsigned char* __restrict__ Bimg,
    const float* __restrict__ sc, const float* __restrict__ bi,
    const unsigned char* __restrict__ residImg, float* __restrict__ Cf,
    unsigned char* __restrict__ Chl,
    int N, int K, int epi)
{
    extern __shared__ __align__(128) unsigned char dsm[];
    __shared__ __align__(8) unsigned long long mbars[2];
    int tid = threadIdx.x, lane = tid & 31, wid = tid >> 5;
    int wm = (wid & 1) << 6, wn = (wid >> 1) << 5;
    long bm = (long)blockIdx.y << 7;
    int bn = blockIdx.x << 7;
    int KT = K >> 5;

    float acc[4][4][4] = {};
    uint32_t sbase = smem_u32(dsm);
    uint32_t mb = smem_u32(mbars);

    if (tid == 0) {
        MBARRIER_INIT(mb, 1);
        MBARRIER_INIT(mb + 8, 1);
    }
    __syncthreads();

    const unsigned char* Ab = Aimg + (long)blockIdx.y * KT * 20480;
    const unsigned char* Bb = Bimg + (long)blockIdx.x * KT * 20480;

    if (tid == 0) {
        MBARRIER_EXPECT_TX(mb, 40960);
        bulkcp(sbase, Ab, mb);
        bulkcp(sbase + 20480, Bb, mb);
        if (KT > 1) {
            MBARRIER_EXPECT_TX(mb + 8, 40960);
            bulkcp(sbase + 40960, Ab + 20480, mb + 8);
            bulkcp(sbase + 61440, Bb + 20480, mb + 8);
        }
    }

    for (int t = 0; t < KT; t++) {
        MBARRIER_WAIT_PARITY(mb + (t & 1) * 8, (t >> 1) & 1);
        uint32_t sAh = sbase + (t & 1) * 40960;
        uint32_t sAl = sAh + 10240;
        uint32_t sBh = sAh + 20480;
        uint32_t sBl = sAh + 30720;
#pragma unroll
        for (int kk = 0; kk < 32; kk += 16) {
            uint32_t ah[4][4], al[4][4], bh[2][4], bl[2][4];
#pragma unroll
            for (int mt = 0; mt < 4; mt++)
                ldsm4(ah[mt], a_addr(sAh, wm + mt * 16, kk, lane));
#pragma unroll
            for (int h = 0; h < 2; h++)
                ldsm4(bh[h], b_addr(sBh, wn + h * 16, kk, lane));
#pragma unroll
            for (int mt = 0; mt < 4; mt++)
#pragma unroll
                for (int nt = 0; nt < 4; nt++)
                    mma16816(acc[mt][nt], ah[mt], &bh[nt >> 1][(nt & 1) * 2]);
#pragma unroll
            for (int h = 0; h < 2; h++)
                ldsm4(bl[h], b_addr(sBl, wn + h * 16, kk, lane));
#pragma unroll
            for (int mt = 0; mt < 4; mt++)
#pragma unroll
                for (int nt = 0; nt < 4; nt++)
                    mma16816(acc[mt][nt], ah[mt], &bl[nt >> 1][(nt & 1) * 2]);
#pragma unroll
            for (int mt = 0; mt < 4; mt++)
                ldsm4(al[mt], a_addr(sAl, wm + mt * 16, kk, lane));
#pragma unroll
            for (int mt = 0; mt < 4; mt++)
#pragma unroll
                for (int nt = 0; nt < 4; nt++)
                    mma16816(acc[mt][nt], al[mt], &bh[nt >> 1][(nt & 1) * 2]);
        }
        __syncthreads();
        if (tid == 0 && t + 2 < KT) {
            uint32_t b8 = mb + (t & 1) * 8;
            uint32_t sb = sbase + (t & 1) * 40960;
            MBARRIER_EXPECT_TX(b8, 40960);
            bulkcp(sb, Ab + (long)(t + 2) * 20480, b8);
            bulkcp(sb + 20480, Bb + (long)(t + 2) * 20480, b8);
        }
    }

    int q = lane >> 2, tq = lane & 3;

    if (epi == 3) {
        float* tile = (float*)dsm;   // [128][129]
#pragma unroll
        for (int nt = 0; nt < 4; nt++) {
            int nl = wn + nt * 8 + tq * 2;
            int n = bn + nl;
            float2 s2 = *(const float2*)(sc + n);
            float2 b2 = *(const float2*)(bi + n);
#pragma unroll
            for (int mt = 0; mt < 4; mt++) {
#pragma unroll
                for (int half = 0; half < 2; half++) {
                    int row = wm + mt * 16 + q + half * 8;
                    long m = bm + row;
                    long off = img_off(m, n, N);
                    __nv_bfloat162 rh = *(const __nv_bfloat162*)(residImg + off);
                    __nv_bfloat162 rl = *(const __nv_bfloat162*)(residImg + off + 10240);
                    tile[row * 129 + nl]     = acc[mt][nt][half * 2 + 0] * s2.x + b2.x +
                        __bfloat162float(rh.x) + __bfloat162float(rl.x);
                    tile[row * 129 + nl + 1] = acc[mt][nt][half * 2 + 1] * s2.y + b2.y +
                        __bfloat162float(rh.y) + __bfloat162float(rl.y);
                }
            }
        }
        __syncthreads();
#pragma unroll
        for (int ci = 0; ci < 16; ci++) {
            int c = wid * 16 + ci;
#pragma unroll
            for (int rc = 0; rc < 4; rc++) {
                int row = rc * 32 + lane;
                long tk = bm + row;
                int b = (int)(tk / 784), tr = (int)(tk % 784);
                Cf[((long)(b * 256 + bn + c)) * 784 + tr] = tile[row * 129 + c];
            }
        }
        return;
    }

#pragma unroll
    for (int nt = 0; nt < 4; nt++) {
        int n = bn + wn + nt * 8 + tq * 2;
        float2 s2 = *(const float2*)(sc + n);
        float2 b2 = *(const float2*)(bi + n);
#pragma unroll
        for (int mt = 0; mt < 4; mt++) {
#pragma unroll
            for (int half = 0; half < 2; half++) {
                long m = bm + wm + mt * 16 + q + half * 8;
                float v0 = acc[mt][nt][half * 2 + 0] * s2.x + b2.x;
                float v1 = acc[mt][nt][half * 2 + 1] * s2.y + b2.y;
                if (epi == 1) {
                    v0 = fmaxf(v0, 0.f);
                    v1 = fmaxf(v1, 0.f);
                } else if (epi == 2) {
                    long off = img_off(m, n, N);
                    __nv_bfloat162 rh = *(const __nv_bfloat162*)(residImg + off);
                    __nv_bfloat162 rl = *(const __nv_bfloat162*)(residImg + off + 10240);
                    v0 += __bfloat162float(rh.x) + __bfloat162float(rl.x);
                    v1 += __bfloat162float(rh.y) + __bfloat162float(rl.y);
                }
                if (epi == 0) {
                    float2 o;
                    o.x = v0; o.y = v1;
                    *(float2*)(Cf + m * N + n) = o;
                } else {
                    img_write(Chl, m, n, N, v0, v1);
                }
            }
        }
    }
}

// ---------------------------------------------------------------------------
// dw0: NCHW input -> blocked image only, xA = x + bn(dw3x3(x))
// ---------------------------------------------------------------------------
__global__ void __launch_bounds__(256) dw0_kernel(
    const float* __restrict__ x, const float* __restrict__ w,
    const float* __restrict__ s, const float* __restrict__ bb)
{
    __shared__ float sx[3][64][29];
    __shared__ float wsm[64][9];
    __shared__ float ssm[64], bsm[64];
    int c0 = blockIdx.x * 64;
    int h = blockIdx.y;
    int b = blockIdx.z;
    int tid = threadIdx.x;

    for (int i = tid; i < 64 * 9; i += 256) {
        int c = i / 9, k = i % 9;
        wsm[c][k] = w[(c0 + c) * 9 + k];
    }
    if (tid < 64) { ssm[tid] = s[c0 + tid]; bsm[tid] = bb[c0 + tid]; }

    for (int i = tid; i < 3 * 64 * 28; i += 256) {
        int row = i / 1792;
        int rem = i % 1792;
        int c = rem / 28, ww = rem % 28;
        int hh = h - 1 + row;
        float v = 0.f;
        if (hh >= 0 && hh < 28)
            v = x[(((long)(b * 256 + c0 + c)) * 28 + hh) * 28 + ww];
        sx[row][c][ww] = v;
    }
    __syncthreads();

    for (int i = tid; i < 64 * 28; i += 256) {
        int cl = i & 63, ww = i >> 6;
        float acc = 0.f;
#pragma unroll
        for (int dy = 0; dy < 3; dy++)
#pragma unroll
            for (int dx = 0; dx < 3; dx++) {
                int w2 = ww + dx - 1;
                if (w2 >= 0 && w2 < 28)
                    acc += wsm[cl][dy * 3 + dx] * sx[dy][cl][w2];
            }
        long t = (long)(b * 28 + h) * 28 + ww;
        float v = sx[1][cl][ww] + ssm[cl] * acc + bsm[cl];
        __nv_bfloat16 hh2, ll2;
        split_bf16(v, hh2, ll2);
        long off = img_off(t, c0 + cl, 256);
        *(__nv_bfloat16*)(g_xAs + off) = hh2;
        *(__nv_bfloat16*)(g_xAs + off + 10240) = ll2;
    }
}

// ---------------------------------------------------------------------------
// dw1: xB = xA + bn(dw3x3(xA)), dw0-style smem staging from the xA image
// ---------------------------------------------------------------------------
__global__ void __launch_bounds__(256) dw1_kernel(
    const float* __restrict__ w, const float* __restrict__ s,
    const float* __restrict__ bb)
{
    __shared__ float sx[3][64][29];
    __shared__ float wsm[64][9];
    __shared__ float ssm[64], bsm[64];
    int c0 = blockIdx.x * 64;
    int h = blockIdx.y;
    int b = blockIdx.z;
    int tid = threadIdx.x;

    for (int i = tid; i < 64 * 9; i += 256) {
        int c = i / 9, k = i % 9;
        wsm[c][k] = w[(c0 + c) * 9 + k];
    }
    if (tid < 64) { ssm[tid] = s[c0 + tid]; bsm[tid] = bb[c0 + tid]; }

    for (int i = tid; i < 3 * 64 * 28; i += 256) {
        int row = i / 1792;
        int rem = i % 1792;
        int c = rem / 28, ww = rem % 28;
        int hh = h - 1 + row;
        float v = 0.f;
        if (hh >= 0 && hh < 28)
            v = img_read(g_xAs, (long)(b * 784 + hh * 28 + ww), c0 + c, 256);
        sx[row][c][ww] = v;
    }
    __syncthreads();

    for (int i = tid; i < 64 * 28; i += 256) {
        int cl = i & 63, ww = i >> 6;
        float acc = 0.f;
#pragma unroll
        for (int dy = 0; dy < 3; dy++)
#pragma unroll
            for (int dx = 0; dx < 3; dx++) {
                int w2 = ww + dx - 1;
                if (w2 >= 0 && w2 < 28)
                    acc += wsm[cl][dy * 3 + dx] * sx[dy][cl][w2];
            }
        long t = (long)(b * 28 + h) * 28 + ww;
        float v = sx[1][cl][ww] + ssm[cl] * acc + bsm[cl];
        __nv_bfloat16 hh2, ll2;
        split_bf16(v, hh2, ll2);
        long off = img_off(t, c0 + cl, 256);
        *(__nv_bfloat16*)(g_xBs + off) = hh2;
        *(__nv_bfloat16*)(g_xBs + off + 10240) = ll2;
    }
}

// ---------------------------------------------------------------------------
// dws: 5x5 depthwise conv, smem-tiled per (batch, head). grid (64, 4), 256 thr
// ---------------------------------------------------------------------------
__global__ void __launch_bounds__(256) dws_kernel(
    const float* __restrict__ w, const float* __restrict__ s,
    const float* __restrict__ bb)
{
    extern __shared__ float sx[];   // [784][17]
    int b = blockIdx.x, head = blockIdx.y;
    int tid = threadIdx.x;
    int kc = tid & 15, tg = tid >> 4;

    for (int i = tid; i < 784 * 16; i += 256) {
        int t = i >> 4, k2 = i & 15;
        sx[t * 17 + k2] = g_qkv[((long)(b * 784 + t)) * 384 + head * 96 + k2];
    }
    __syncthreads();

    int ch = head * 16 + kc;
    float wr[25];
#pragma unroll
    for (int k = 0; k < 25; k++) wr[k] = w[ch * 25 + k];
    float sv = s[ch], bv = bb[ch];

    for (int j = 0; j < 49; j++) {
        int t = tg + (j << 4);
        int h = t / 28, ww = t % 28;
        float acc = 0.f;
#pragma unroll
        for (int dy = 0; dy < 5; dy++) {
            int h2 = h + dy - 2;
            if (h2 < 0 || h2 >= 28) continue;
#pragma unroll
            for (int dx = 0; dx < 5; dx++) {
                int w2 = ww + dx - 2;
                if (w2 < 0 || w2 >= 28) continue;
                acc += wr[dy * 5 + dx] * sx[(h2 * 28 + w2) * 17 + kc];
            }
        }
        g_q2[((long)(b * 784 + t)) * 64 + ch] = sv * acc + bv;
    }
}

// ---------------------------------------------------------------------------
// per-window attention (7x7 = 49 tokens), f32x2 math (R13 form)
// ---------------------------------------------------------------------------
__global__ void __launch_bounds__(128) attn_kernel(const float* __restrict__ pos)
{
    int wi = blockIdx.x >> 2, wj = blockIdx.x & 3;
    int head = blockIdx.y, b = blockIdx.z;
    int tid = threadIdx.x;

    __shared__ __align__(8) float sq[49 * 18];
    __shared__ __align__(8) float sk[49 * 18];
    __shared__ __align__(16) float sv[49 * 64];
    __shared__ __align__(8) float ss[49 * 50];
    __shared__ int stok[49];

    if (tid < 49)
        stok[tid] = b * 784 + (wi * 7 + tid / 7) * 28 + wj * 7 + (tid % 7);
    __syncthreads();

    for (int i = tid; i < 49 * 16; i += 128) {
        int r = i >> 4, c = i & 15;
        long t = stok[r];
        sq[r * 18 + c] = g_q2[t * 64 + head * 16 + c];
        sk[r * 18 + c] = g_qkv[t * 384 + head * 96 + 16 + c];
    }
    for (int i = tid; i < 49 * 64; i += 128) {
        int r = i >> 6, c = i & 63;
        sv[i] = g_qkv[(long)stok[r] * 384 + head * 96 + 32 + c];
    }
    __syncthreads();

    const float* pe = pos + head * 49 * 49;
    for (int i = tid; i < 49 * 49; i += 128) {
        int qr = i / 49, kr = i % 49;
        unsigned long long d2 = pack2f(0.f, 0.f);
#pragma unroll
        for (int cc = 0; cc < 8; cc++) {
            unsigned long long a2 = *(const unsigned long long*)&sq[qr * 18 + cc * 2];
            unsigned long long b2 = *(const unsigned long long*)&sk[kr * 18 + cc * 2];
            ffma2(d2, a2, b2);
        }
        float2 f = unpack2f(d2);
        ss[qr * 50 + kr] = (f.x + f.y) * 0.25f + pe[i];
    }
    __syncthreads();

    {   // softmax, 2 threads per row + shfl combine
        int r = tid >> 1, hf = tid & 1;
        bool act = r < 49;
        float* row = ss + (act ? r : 0) * 50;
        int k0 = hf ? 25 : 0, cnt = hf ? 24 : 25;
        float mx = -1e30f;
        for (int k = 0; k < cnt; k++) mx = fmaxf(mx, row[k0 + k]);
        mx = fmaxf(mx, __shfl_xor_sync(0xffffffffu, mx, 1));
        float ev[25];
        float sum = 0.f;
        for (int k = 0; k < cnt; k++) {
            ev[k] = __expf(row[k0 + k] - mx);
            sum += ev[k];
        }
        sum += __shfl_xor_sync(0xffffffffu, sum, 1);
        float inv = 1.f / sum;
        if (act)
            for (int k = 0; k < cnt; k++) row[k0 + k] = ev[k] * inv;
    }
    __syncthreads();

    for (int i = tid; i < 49 * 16; i += 128) {
        int qr = i >> 4, d0 = (i & 15) << 2;
        unsigned long long a01 = pack2f(0.f, 0.f), a23 = pack2f(0.f, 0.f);
        for (int k = 0; k < 49; k++) {
            float p = ss[qr * 50 + k];
            unsigned long long p2 = pack2f(p, p);
            ffma2(a01, p2, *(const unsigned long long*)&sv[k * 64 + d0]);
            ffma2(a23, p2, *(const unsigned long long*)&sv[k * 64 + d0 + 2]);
        }
        float2 f01 = unpack2f(a01), f23 = unpack2f(a23);
        float r0 = fmaxf(f01.x, 0.f), r1 = fmaxf(f01.y, 0.f);
        float r2 = fmaxf(f23.x, 0.f), r3 = fmaxf(f23.y, 0.f);
        long t = stok[qr];
        img_write(g_obs, t, head * 64 + d0, 256, r0, r1);
        img_write(g_obs, t, head * 64 + d0 + 2, 256, r2, r3);
    }
}

// ---------------------------------------------------------------------------
extern "C" void kernel_launch(void* const* d_in, const int* in_sizes, int n_in,
                              void* d_out, int out_size)
{
    const float* in[32];
    for (int i = 0; i < n_in && i < 32; i++) in[i] = (const float*)d_in[i];

    int idw0, idw1, iffn0, iffn1, iqkv, idws, iproj, ipos;
    if (in_sizes[4] > 100000) { // reference-signature order
        idw0 = 1;  iffn0 = 4;  iqkv = 10; idws = 13; iproj = 16;
        ipos = 19; idw1 = 20;  iffn1 = 23;
    } else {                    // setup_inputs dict order
        idw0 = 1;  idw1 = 4;   iffn0 = 7;  iffn1 = 13;
        iqkv = 19; idws = 22;  iproj = 25; ipos = 28;
    }

    const float* x     = in[0];
    const float* dw0_w = in[idw0],  * dw0_s = in[idw0 + 1], * dw0_b = in[idw0 + 2];
    const float* dw1_w = in[idw1],  * dw1_s = in[idw1 + 1], * dw1_b = in[idw1 + 2];
    const float* f0w1 = in[iffn0],     * f0s1 = in[iffn0 + 1], * f0b1 = in[iffn0 + 2];
    const float* f0w2 = in[iffn0 + 3], * f0s2 = in[iffn0 + 4], * f0b2 = in[iffn0 + 5];
    const float* f1w1 = in[iffn1],     * f1s1 = in[iffn1 + 1], * f1b1 = in[iffn1 + 2];
    const float* f1w2 = in[iffn1 + 3], * f1s2 = in[iffn1 + 4], * f1b2 = in[iffn1 + 5];
    const float* qkv_w = in[iqkv],  * qkv_s = in[iqkv + 1],  * qkv_b = in[iqkv + 2];
    const float* dws_w = in[idws],  * dws_s = in[idws + 1],  * dws_b = in[idws + 2];
    const float* proj_w = in[iproj], * proj_s = in[iproj + 1], * proj_b = in[iproj + 2];
    const float* pos = in[ipos];

    float* pqkv;
    unsigned char *pxAs, *phs, *pobs, *pxBs, *pwtB;
    cudaGetSymbolAddress((void**)&pqkv, g_qkv);
    cudaGetSymbolAddress((void**)&pxAs, g_xAs);
    cudaGetSymbolAddress((void**)&phs,  g_hs);
    cudaGetSymbolAddress((void**)&pobs, g_obs);
    cudaGetSymbolAddress((void**)&pxBs, g_xBs);
    cudaGetSymbolAddress((void**)&pwtB, g_wtB);

    const int SMEM_GEMM = 81920;
    cudaFuncSetAttribute(mm_gemm, cudaFuncAttributeMaxDynamicSharedMemorySize,
                         SMEM_GEMM);
    const int SMEM_DWS = 784 * 17 * 4;
    cudaFuncSetAttribute(dws_kernel, cudaFuncAttributeMaxDynamicSharedMemorySize,
                         SMEM_DWS);

    wconv_all<<<(688128 + 255) / 256, 256>>>(f0w1, f0w2, qkv_w, proj_w, f1w1,
                                             f1w2, pwtB);

    // 1. xA = x + bn(dw3x3(x))  -> image
    dw0_kernel<<<dim3(4, 28, 64), 256>>>(x, dw0_w, dw0_s, dw0_b);

    // 2. ffn0 (h image; then in-place xA image += ffn)
    mm_gemm<<<dim3(4, 392), 256, SMEM_GEMM>>>(
        pxAs, pwtB + WB_F0W1, f0s1, f0b1, nullptr, nullptr, phs, 512, 256, 1);
    mm_gemm<<<dim3(2, 392), 256, SMEM_GEMM>>>(
        phs, pwtB + WB_F0W2, f0s2, f0b2, pxAs, nullptr, pxAs, 256, 512, 2);

    // 3. attention
    mm_gemm<<<dim3(3, 392), 256, SMEM_GEMM>>>(
        pxAs, pwtB + WB_QKV, qkv_s, qkv_b, nullptr, pqkv, nullptr, 384, 256, 0);
    dws_kernel<<<dim3(64, 4), 256, SMEM_DWS>>>(dws_w, dws_s, dws_b);
    attn_kernel<<<dim3(16, 4, 64), 128>>>(pos);
    mm_gemm<<<dim3(2, 392), 256, SMEM_GEMM>>>(
        pobs, pwtB + WB_PROJ, proj_s, proj_b, pxAs, nullptr, pxAs, 256, 256, 2);

    // 4. xB image = xA + bn(dw3x3(xA))
    dw1_kernel<<<dim3(4, 28, 64), 256>>>(dw1_w, dw1_s, dw1_b);

    // 5. ffn1: h image, then final GEMM -> NCHW d_out (epi=3, resid xB image)
    mm_gemm<<<dim3(4, 392), 256, SMEM_GEMM>>>(
        pxBs, pwtB + WB_F1W1, f1s1, f1b1, nullptr, nullptr, phs, 512, 256, 1);
    mm_gemm<<<dim3(2, 392), 256, SMEM_GEMM>>>(
        phs, pwtB + WB_F1W2, f1s2, f1b2, pxBs, (float*)d_out, nullptr,
        256, 512, 3);
}

// round 16
// speedup vs baseline: 1.0476x; 1.0376x over previous
#include <cuda_runtime.h>
#include <cuda_bf16.h>
#include <cstdint>

// ---------------------------------------------------------------------------
// EfficientViT block. HMMA mma.sync bf16 hi/lo-split GEMMs (persistent CTAs,
// bulk-load mainloop, bulk-store epilogue), blocked bf16 images as the only
// activation storage, smem-tiled dws, R13 window attention + per-token dw1.
// ---------------------------------------------------------------------------

#define TOK   50176

__device__ float g_qkv[TOK * 384];
__device__ float g_q2[TOK * 64];

// blocked hi/lo bf16 images: [128 rows x 32 k] tiles, stride 40, hi+lo = 20480B
__device__ __align__(16) unsigned char g_xAs[TOK * 256 * 5];
__device__ __align__(16) unsigned char g_hs [TOK * 512 * 5];
__device__ __align__(16) unsigned char g_obs[TOK * 256 * 5];
__device__ __align__(16) unsigned char g_xBs[TOK * 256 * 5];
__device__ __align__(16) unsigned char g_wtB[3440640];

#define WB_F0W1 0
#define WB_F0W2 655360
#define WB_QKV  1310720
#define WB_PROJ 1802240
#define WB_F1W1 2129920
#define WB_F1W2 2785280

__device__ __forceinline__ uint32_t smem_u32(const void* p) {
    uint32_t a;
    asm("{ .reg .u64 t; cvta.to.shared.u64 t, %1; cvt.u32.u64 %0, t; }"
        : "=r"(a) : "l"(p));
    return a;
}
__device__ __forceinline__ void ldsm4(uint32_t* r, uint32_t addr) {
    asm volatile("ldmatrix.sync.aligned.m8n8.x4.shared.b16 {%0,%1,%2,%3}, [%4];"
        : "=r"(r[0]), "=r"(r[1]), "=r"(r[2]), "=r"(r[3]) : "r"(addr));
}
__device__ __forceinline__ void mma16816(float* c, const uint32_t* a,
                                         const uint32_t* b) {
    asm volatile(
        "mma.sync.aligned.m16n8k16.row.col.f32.bf16.bf16.f32 "
        "{%0,%1,%2,%3}, {%4,%5,%6,%7}, {%8,%9}, {%0,%1,%2,%3};"
        : "+f"(c[0]), "+f"(c[1]), "+f"(c[2]), "+f"(c[3])
        : "r"(a[0]), "r"(a[1]), "r"(a[2]), "r"(a[3]), "r"(b[0]), "r"(b[1]));
}

// packed f32x2 FMA
__device__ __forceinline__ unsigned long long pack2f(float lo, float hi) {
    unsigned long long r;
    asm("mov.b64 %0, {%1,%2};" : "=l"(r) : "f"(lo), "f"(hi));
    return r;
}
__device__ __forceinline__ void ffma2(unsigned long long& d,
                                      unsigned long long a,
                                      unsigned long long b) {
    asm("fma.rn.f32x2 %0, %1, %2, %3;" : "=l"(d) : "l"(a), "l"(b), "l"(d));
}
__device__ __forceinline__ float2 unpack2f(unsigned long long v) {
    float2 f;
    asm("mov.b64 {%0,%1}, %2;" : "=f"(f.x), "=f"(f.y) : "l"(v));
    return f;
}

#define MBARRIER_INIT(mbar_addr, count) \
    asm volatile("mbarrier.init.shared.b64 [%0], %1;" \
        :: "r"((uint32_t)(mbar_addr)), "r"((uint32_t)(count)) : "memory")
#define MBARRIER_EXPECT_TX(mbar_addr, tx_bytes) \
    asm volatile("mbarrier.arrive.expect_tx.shared.b64 _, [%0], %1;" \
        :: "r"((uint32_t)(mbar_addr)), "r"((uint32_t)(tx_bytes)) : "memory")
#define MBARRIER_WAIT_PARITY(mbar_addr, parity) do { \
    uint32_t _mbar = (uint32_t)(mbar_addr); \
    uint32_t _par = (uint32_t)(parity); \
    uint32_t _done; \
    asm volatile( \
        "{\n\t.reg .pred p;\n\t" \
        "mbarrier.try_wait.parity.acquire.cta.shared::cta.b64 p, [%1], %2;\n\t" \
        "selp.b32 %0, 1, 0, p;\n\t}" \
        : "=r"(_done) : "r"(_mbar), "r"(_par) : "memory"); \
    if (!_done) { \
        asm volatile( \
            "{\n\t.reg .pred P1;\n\t" \
            "WAIT_LOOP_%=:\n\t" \
            "mbarrier.try_wait.parity.acquire.cta.shared::cta.b64 P1, [%0], %1, 0x989680;\n\t" \
            "@P1 bra.uni WAIT_DONE_%=;\n\t" \
            "bra.uni WAIT_LOOP_%=;\n\t" \
            "WAIT_DONE_%=:\n\t}" \
            :: "r"(_mbar), "r"(_par) : "memory"); \
    } \
} while (0)

__device__ __forceinline__ void bulkcp(uint32_t dst, const void* src,
                                       uint32_t mbar) {
    asm volatile(
        "cp.async.bulk.shared::cta.global.mbarrier::complete_tx::bytes "
        "[%0], [%1], %2, [%3];"
        :: "r"(dst), "l"(src), "r"(20480u), "r"(mbar) : "memory");
}

// blocked-image byte offset of (row, col) hi element; lo at +10240
__device__ __forceinline__ long img_off(long row, int col, int Kd) {
    return ((row >> 7) * (Kd >> 5) + (col >> 5)) * 20480L +
           (row & 127) * 80 + (col & 31) * 2;
}
__device__ __forceinline__ float img_read(const unsigned char* img, long row,
                                          int col, int Kd) {
    long off = img_off(row, col, Kd);
    return __bfloat162float(*(const __nv_bfloat16*)(img + off)) +
           __bfloat162float(*(const __nv_bfloat16*)(img + off + 10240));
}

#define TS 40
__device__ __forceinline__ uint32_t a_addr(uint32_t base, int m, int k, int lane) {
    int g = lane >> 3, r = lane & 7;
    return base + ((m + ((g & 1) << 3) + r) * TS + k + ((g >> 1) << 3)) * 2;
}
__device__ __forceinline__ uint32_t b_addr(uint32_t base, int n, int k, int lane) {
    int g = lane >> 3, r = lane & 7;
    return base + ((n + ((g >> 1) << 3) + r) * TS + k + ((g & 1) << 3)) * 2;
}

__device__ __forceinline__ void split_bf16(float v, __nv_bfloat16& h,
                                           __nv_bfloat16& l) {
    h = __float2bfloat16(v);
    l = __float2bfloat16(v - __bfloat162float(h));
}
__device__ __forceinline__ void img_write(unsigned char* img, long row, int col,
                                          int Kd, float v0, float v1) {
    __nv_bfloat16 h0, l0, h1, l1;
    split_bf16(v0, h0, l0);
    split_bf16(v1, h1, l1);
    long off = img_off(row, col, Kd);
    __nv_bfloat162 hv, lv;
    hv.x = h0; hv.y = h1;
    lv.x = l0; lv.y = l1;
    *(__nv_bfloat162*)(img + off) = hv;
    *(__nv_bfloat162*)(img + off + 10240) = lv;
}

// ---------------------------------------------------------------------------
// All-weights split into blocked images, one launch
// ---------------------------------------------------------------------------
__global__ void wconv_all(const float* __restrict__ w0, const float* __restrict__ w1,
                          const float* __restrict__ w2, const float* __restrict__ w3,
                          const float* __restrict__ w4, const float* __restrict__ w5,
                          unsigned char* __restrict__ dst) {
    long i = (long)blockIdx.x * 256 + threadIdx.x;
    if (i >= 688128) return;
    const long cum[7] = {0, 131072, 262144, 360448, 425984, 557056, 688128};
    const long ob[6] = {WB_F0W1, WB_F0W2, WB_QKV, WB_PROJ, WB_F1W1, WB_F1W2};
    const int Ks[6] = {256, 512, 256, 256, 256, 512};
    const float* srcs[6] = {w0, w1, w2, w3, w4, w5};
    int s = 0;
    while (i >= cum[s + 1]) s++;
    long j = i - cum[s];
    int K = Ks[s];
    long n = j / K;
    int k = (int)(j % K);
    __nv_bfloat16 h, l;
    split_bf16(srcs[s][j], h, l);
    long off = ob[s] + img_off(n, k, K);
    *(__nv_bfloat16*)(dst + off) = h;
    *(__nv_bfloat16*)(dst + off + 10240) = l;
}

// ---------------------------------------------------------------------------
// Persistent HMMA GEMM. epi: 0 fp32 out ; 1 relu->img ; 2 resid(img)+ ->img
//                       3 resid(img)+ -> NCHW fp32 transpose out
// epi 1/2 use smem-staged output + cp.async.bulk S2G (contiguous 81920B).
// ---------------------------------------------------------------------------
__global__ void __launch_bounds__(256, 2) mm_gemm(
    const unsigned char* __restrict__ Aimg, const unsigned char* __restrict__ Bimg,
    const float* __restrict__ sc, const float* __restrict__ bi,
    const unsigned char* __restrict__ residImg, float* __restrict__ Cf,
    unsigned char* __restrict__ Chl,
    int N, int K, int epi, int NX, int numTiles)
{
    extern __shared__ __align__(128) unsigned char dsm[];
    __shared__ __align__(8) unsigned long long mbars[2];
    int tid = threadIdx.x, lane = tid & 31, wid = tid >> 5;
    int wm = (wid & 1) << 6, wn = (wid >> 1) << 5;
    int KT = K >> 5;
    uint32_t sbase = smem_u32(dsm);
    uint32_t mb = smem_u32(mbars);

    if (tid == 0) {
        MBARRIER_INIT(mb, 1);
        MBARRIER_INIT(mb + 8, 1);
    }
    __syncthreads();

    unsigned int aph = 0;   // running half-stage counter (KT is even)

    for (int tile = blockIdx.x; tile < numTiles; tile += gridDim.x) {
        int bx = tile % NX, by = tile / NX;
        long bm = (long)by << 7;
        int bn = bx << 7;
        const unsigned char* Ab = Aimg + (long)by * KT * 20480;
        const unsigned char* Bb = Bimg + (long)bx * KT * 20480;

        float acc[4][4][4];
#pragma unroll
        for (int i = 0; i < 4; i++)
#pragma unroll
            for (int j = 0; j < 4; j++)
#pragma unroll
                for (int kk2 = 0; kk2 < 4; kk2++) acc[i][j][kk2] = 0.f;

        if (tid == 0) {
            MBARRIER_EXPECT_TX(mb, 40960);
            bulkcp(sbase, Ab, mb);
            bulkcp(sbase + 20480, Bb, mb);
            MBARRIER_EXPECT_TX(mb + 8, 40960);
            bulkcp(sbase + 40960, Ab + 20480, mb + 8);
            bulkcp(sbase + 61440, Bb + 20480, mb + 8);
        }

        for (int t = 0; t < KT; t++) {
            MBARRIER_WAIT_PARITY(mb + (t & 1) * 8, (aph + (t >> 1)) & 1);
            uint32_t sAh = sbase + (t & 1) * 40960;
            uint32_t sAl = sAh + 10240;
            uint32_t sBh = sAh + 20480;
            uint32_t sBl = sAh + 30720;
#pragma unroll
            for (int kk = 0; kk < 32; kk += 16) {
                uint32_t ah[4][4], al[4][4], bh[2][4], bl[2][4];
#pragma unroll
                for (int mt = 0; mt < 4; mt++)
                    ldsm4(ah[mt], a_addr(sAh, wm + mt * 16, kk, lane));
#pragma unroll
                for (int h = 0; h < 2; h++)
                    ldsm4(bh[h], b_addr(sBh, wn + h * 16, kk, lane));
#pragma unroll
                for (int mt = 0; mt < 4; mt++)
#pragma unroll
                    for (int nt = 0; nt < 4; nt++)
                        mma16816(acc[mt][nt], ah[mt], &bh[nt >> 1][(nt & 1) * 2]);
#pragma unroll
                for (int h = 0; h < 2; h++)
                    ldsm4(bl[h], b_addr(sBl, wn + h * 16, kk, lane));
#pragma unroll
                for (int mt = 0; mt < 4; mt++)
#pragma unroll
                    for (int nt = 0; nt < 4; nt++)
                        mma16816(acc[mt][nt], ah[mt], &bl[nt >> 1][(nt & 1) * 2]);
#pragma unroll
                for (int mt = 0; mt < 4; mt++)
                    ldsm4(al[mt], a_addr(sAl, wm + mt * 16, kk, lane));
#pragma unroll
                for (int mt = 0; mt < 4; mt++)
#pragma unroll
                    for (int nt = 0; nt < 4; nt++)
                        mma16816(acc[mt][nt], al[mt], &bh[nt >> 1][(nt & 1) * 2]);
            }
            __syncthreads();
            if (tid == 0 && t + 2 < KT) {
                uint32_t b8 = mb + (t & 1) * 8;
                uint32_t sb = sbase + (t & 1) * 40960;
                MBARRIER_EXPECT_TX(b8, 40960);
                bulkcp(sb, Ab + (long)(t + 2) * 20480, b8);
                bulkcp(sb + 20480, Bb + (long)(t + 2) * 20480, b8);
            }
        }
        aph += (unsigned)(KT >> 1);

        int q = lane >> 2, tq = lane & 3;

        if (epi == 3) {
            float* tile2 = (float*)dsm;   // [128][129]
#pragma unroll
            for (int nt = 0; nt < 4; nt++) {
                int nl = wn + nt * 8 + tq * 2;
                int n = bn + nl;
                float2 s2 = *(const float2*)(sc + n);
                float2 b2 = *(const float2*)(bi + n);
#pragma unroll
                for (int mt = 0; mt < 4; mt++) {
#pragma unroll
                    for (int half = 0; half < 2; half++) {
                        int row = wm + mt * 16 + q + half * 8;
                        long m = bm + row;
                        long off = img_off(m, n, N);
                        __nv_bfloat162 rh = *(const __nv_bfloat162*)(residImg + off);
                        __nv_bfloat162 rl = *(const __nv_bfloat162*)(residImg + off + 10240);
                        tile2[row * 129 + nl]     = acc[mt][nt][half * 2 + 0] * s2.x + b2.x +
                            __bfloat162float(rh.x) + __bfloat162float(rl.x);
                        tile2[row * 129 + nl + 1] = acc[mt][nt][half * 2 + 1] * s2.y + b2.y +
                            __bfloat162float(rh.y) + __bfloat162float(rl.y);
                    }
                }
            }
            __syncthreads();
#pragma unroll
            for (int ci = 0; ci < 16; ci++) {
                int c = wid * 16 + ci;
#pragma unroll
                for (int rc = 0; rc < 4; rc++) {
                    int row = rc * 32 + lane;
                    long tk = bm + row;
                    int b = (int)(tk / 784), tr = (int)(tk % 784);
                    Cf[((long)(b * 256 + bn + c)) * 784 + tr] = tile2[row * 129 + c];
                }
            }
            __syncthreads();
        } else if (epi == 0) {
#pragma unroll
            for (int nt = 0; nt < 4; nt++) {
                int n = bn + wn + nt * 8 + tq * 2;
                float2 s2 = *(const float2*)(sc + n);
                float2 b2 = *(const float2*)(bi + n);
#pragma unroll
                for (int mt = 0; mt < 4; mt++) {
#pragma unroll
                    for (int half = 0; half < 2; half++) {
                        long m = bm + wm + mt * 16 + q + half * 8;
                        float2 o;
                        o.x = acc[mt][nt][half * 2 + 0] * s2.x + b2.x;
                        o.y = acc[mt][nt][half * 2 + 1] * s2.y + b2.y;
                        *(float2*)(Cf + m * N + n) = o;
                    }
                }
            }
            __syncthreads();
        } else {
            // epi 1/2: stage blocked-image output in smem, bulk-store 81920 B
#pragma unroll
            for (int nt = 0; nt < 4; nt++) {
                int nl = wn + nt * 8 + tq * 2;
                int n = bn + nl;
                float2 s2 = *(const float2*)(sc + n);
                float2 b2 = *(const float2*)(bi + n);
#pragma unroll
                for (int mt = 0; mt < 4; mt++) {
#pragma unroll
                    for (int half = 0; half < 2; half++) {
                        int row = wm + mt * 16 + q + half * 8;
                        long m = bm + row;
                        float v0 = acc[mt][nt][half * 2 + 0] * s2.x + b2.x;
                        float v1 = acc[mt][nt][half * 2 + 1] * s2.y + b2.y;
                        if (epi == 1) {
                            v0 = fmaxf(v0, 0.f);
                            v1 = fmaxf(v1, 0.f);
                        } else {
                            long off = img_off(m, n, N);
                            __nv_bfloat162 rh = *(const __nv_bfloat162*)(residImg + off);
                            __nv_bfloat162 rl = *(const __nv_bfloat162*)(residImg + off + 10240);
                            v0 += __bfloat162float(rh.x) + __bfloat162float(rl.x);
                            v1 += __bfloat162float(rh.y) + __bfloat162float(rl.y);
                        }
                        __nv_bfloat16 h0, l0, h1, l1;
                        split_bf16(v0, h0, l0);
                        split_bf16(v1, h1, l1);
                        __nv_bfloat162 hv, lv;
                        hv.x = h0; hv.y = h1;
                        lv.x = l0; lv.y = l1;
                        uint32_t so = (uint32_t)((nl >> 5) * 20480 + row * 80 +
                                                 (nl & 31) * 2);
                        *(__nv_bfloat162*)(dsm + so) = hv;
                        *(__nv_bfloat162*)(dsm + so + 10240) = lv;
                    }
                }
            }
            __syncthreads();
            if (tid == 0) {
                asm volatile("fence.proxy.async.shared::cta;" ::: "memory");
                unsigned char* gdst =
                    Chl + ((long)by * (N >> 5) + ((long)bx << 2)) * 20480;
                asm volatile(
                    "cp.async.bulk.global.shared::cta.bulk_group [%0], [%1], %2;"
                    :: "l"(gdst), "r"(sbase), "r"(81920u) : "memory");
                asm volatile("cp.async.bulk.commit_group;" ::: "memory");
                asm volatile("cp.async.bulk.wait_group 0;" ::: "memory");
            }
            __syncthreads();
        }
    }
}

// ---------------------------------------------------------------------------
// dw0: NCHW input -> blocked image only, xA = x + bn(dw3x3(x))
// ---------------------------------------------------------------------------
__global__ void __launch_bounds__(256) dw0_kernel(
    const float* __restrict__ x, const float* __restrict__ w,
    const float* __restrict__ s, const float* __restrict__ bb)
{
    __shared__ float sx[3][64][29];
    __shared__ float wsm[64][9];
    __shared__ float ssm[64], bsm[64];
    int c0 = blockIdx.x * 64;
    int h = blockIdx.y;
    int b = blockIdx.z;
    int tid = threadIdx.x;

    for (int i = tid; i < 64 * 9; i += 256) {
        int c = i / 9, k = i % 9;
        wsm[c][k] = w[(c0 + c) * 9 + k];
    }
    if (tid < 64) { ssm[tid] = s[c0 + tid]; bsm[tid] = bb[c0 + tid]; }

    for (int i = tid; i < 3 * 64 * 28; i += 256) {
        int row = i / 1792;
        int rem = i % 1792;
        int c = rem / 28, ww = rem % 28;
        int hh = h - 1 + row;
        float v = 0.f;
        if (hh >= 0 && hh < 28)
            v = x[(((long)(b * 256 + c0 + c)) * 28 + hh) * 28 + ww];
        sx[row][c][ww] = v;
    }
    __syncthreads();

    for (int i = tid; i < 64 * 28; i += 256) {
        int cl = i & 63, ww = i >> 6;
        float acc = 0.f;
#pragma unroll
        for (int dy = 0; dy < 3; dy++)
#pragma unroll
            for (int dx = 0; dx < 3; dx++) {
                int w2 = ww + dx - 1;
                if (w2 >= 0 && w2 < 28)
                    acc += wsm[cl][dy * 3 + dx] * sx[dy][cl][w2];
            }
        long t = (long)(b * 28 + h) * 28 + ww;
        float v = sx[1][cl][ww] + ssm[cl] * acc + bsm[cl];
        __nv_bfloat16 hh2, ll2;
        split_bf16(v, hh2, ll2);
        long off = img_off(t, c0 + cl, 256);
        *(__nv_bfloat16*)(g_xAs + off) = hh2;
        *(__nv_bfloat16*)(g_xAs + off + 10240) = ll2;
    }
}

// ---------------------------------------------------------------------------
// dw1 (R13 form): per-token block, channel-major coalesced image reads
// ---------------------------------------------------------------------------
__global__ void __launch_bounds__(256) dw1_kernel(
    const float* __restrict__ w, const float* __restrict__ s,
    const float* __restrict__ bb)
{
    int t = blockIdx.x;
    int c = threadIdx.x;
    int b = t / 784, rem = t % 784, h = rem / 28, ww = rem % 28;
    float wr[9];
#pragma unroll
    for (int k = 0; k < 9; k++) wr[k] = w[c * 9 + k];
    float acc = 0.f, center = 0.f;
#pragma unroll
    for (int dy = 0; dy < 3; dy++) {
        int h2 = h + dy - 1;
        if (h2 < 0 || h2 >= 28) continue;
#pragma unroll
        for (int dx = 0; dx < 3; dx++) {
            int w2 = ww + dx - 1;
            if (w2 < 0 || w2 >= 28) continue;
            float v = img_read(g_xAs, (long)(b * 784 + h2 * 28 + w2), c, 256);
            acc += wr[dy * 3 + dx] * v;
            if (dy == 1 && dx == 1) center = v;
        }
    }
    float out = center + s[c] * acc + bb[c];
    __nv_bfloat16 hh, ll;
    split_bf16(out, hh, ll);
    long off = img_off(t, c, 256);
    *(__nv_bfloat16*)(g_xBs + off) = hh;
    *(__nv_bfloat16*)(g_xBs + off + 10240) = ll;
}

// ---------------------------------------------------------------------------
// dws: 5x5 depthwise conv, smem-tiled per (batch, head). grid (64, 4), 256 thr
// ---------------------------------------------------------------------------
__global__ void __launch_bounds__(256) dws_kernel(
    const float* __restrict__ w, const float* __restrict__ s,
    const float* __restrict__ bb)
{
    extern __shared__ float sx[];   // [784][17]
    int b = blockIdx.x, head = blockIdx.y;
    int tid = threadIdx.x;
    int kc = tid & 15, tg = tid >> 4;

    for (int i = tid; i < 784 * 16; i += 256) {
        int t = i >> 4, k2 = i & 15;
        sx[t * 17 + k2] = g_qkv[((long)(b * 784 + t)) * 384 + head * 96 + k2];
    }
    __syncthreads();

    int ch = head * 16 + kc;
    float wr[25];
#pragma unroll
    for (int k = 0; k < 25; k++) wr[k] = w[ch * 25 + k];
    float sv = s[ch], bv = bb[ch];

    for (int j = 0; j < 49; j++) {
        int t = tg + (j << 4);
        int h = t / 28, ww = t % 28;
        float acc = 0.f;
#pragma unroll
        for (int dy = 0; dy < 5; dy++) {
            int h2 = h + dy - 2;
            if (h2 < 0 || h2 >= 28) continue;
#pragma unroll
            for (int dx = 0; dx < 5; dx++) {
                int w2 = ww + dx - 2;
                if (w2 < 0 || w2 >= 28) continue;
                acc += wr[dy * 5 + dx] * sx[(h2 * 28 + w2) * 17 + kc];
            }
        }
        g_q2[((long)(b * 784 + t)) * 64 + ch] = sv * acc + bv;
    }
}

// ---------------------------------------------------------------------------
// per-window attention (7x7 = 49 tokens), f32x2 math (R13 form)
// ---------------------------------------------------------------------------
__global__ void __launch_bounds__(128) attn_kernel(const float* __restrict__ pos)
{
    int wi = blockIdx.x >> 2, wj = blockIdx.x & 3;
    int head = blockIdx.y, b = blockIdx.z;
    int tid = threadIdx.x;

    __shared__ __align__(8) float sq[49 * 18];
    __shared__ __align__(8) float sk[49 * 18];
    __shared__ __align__(16) float sv[49 * 64];
    __shared__ __align__(8) float ss[49 * 50];
    __shared__ int stok[49];

    if (tid < 49)
        stok[tid] = b * 784 + (wi * 7 + tid / 7) * 28 + wj * 7 + (tid % 7);
    __syncthreads();

    for (int i = tid; i < 49 * 16; i += 128) {
        int r = i >> 4, c = i & 15;
        long t = stok[r];
        sq[r * 18 + c] = g_q2[t * 64 + head * 16 + c];
        sk[r * 18 + c] = g_qkv[t * 384 + head * 96 + 16 + c];
    }
    for (int i = tid; i < 49 * 64; i += 128) {
        int r = i >> 6, c = i & 63;
        sv[i] = g_qkv[(long)stok[r] * 384 + head * 96 + 32 + c];
    }
    __syncthreads();

    const float* pe = pos + head * 49 * 49;
    for (int i = tid; i < 49 * 49; i += 128) {
        int qr = i / 49, kr = i % 49;
        unsigned long long d2 = pack2f(0.f, 0.f);
#pragma unroll
        for (int cc = 0; cc < 8; cc++) {
            unsigned long long a2 = *(const unsigned long long*)&sq[qr * 18 + cc * 2];
            unsigned long long b2 = *(const unsigned long long*)&sk[kr * 18 + cc * 2];
            ffma2(d2, a2, b2);
        }
        float2 f = unpack2f(d2);
        ss[qr * 50 + kr] = (f.x + f.y) * 0.25f + pe[i];
    }
    __syncthreads();

    {   // softmax, 2 threads per row + shfl combine
        int r = tid >> 1, hf = tid & 1;
        bool act = r < 49;
        float* row = ss + (act ? r : 0) * 50;
        int k0 = hf ? 25 : 0, cnt = hf ? 24 : 25;
        float mx = -1e30f;
        for (int k = 0; k < cnt; k++) mx = fmaxf(mx, row[k0 + k]);
        mx = fmaxf(mx, __shfl_xor_sync(0xffffffffu, mx, 1));
        float ev[25];
        float sum = 0.f;
        for (int k = 0; k < cnt; k++) {
            ev[k] = __expf(row[k0 + k] - mx);
            sum += ev[k];
        }
        sum += __shfl_xor_sync(0xffffffffu, sum, 1);
        float inv = 1.f / sum;
        if (act)
            for (int k = 0; k < cnt; k++) row[k0 + k] = ev[k] * inv;
    }
    __syncthreads();

    for (int i = tid; i < 49 * 16; i += 128) {
        int qr = i >> 4, d0 = (i & 15) << 2;
        unsigned long long a01 = pack2f(0.f, 0.f), a23 = pack2f(0.f, 0.f);
        for (int k = 0; k < 49; k++) {
            float p = ss[qr * 50 + k];
            unsigned long long p2 = pack2f(p, p);
            ffma2(a01, p2, *(const unsigned long long*)&sv[k * 64 + d0]);
            ffma2(a23, p2, *(const unsigned long long*)&sv[k * 64 + d0 + 2]);
        }
        float2 f01 = unpack2f(a01), f23 = unpack2f(a23);
        float r0 = fmaxf(f01.x, 0.f), r1 = fmaxf(f01.y, 0.f);
        float r2 = fmaxf(f23.x, 0.f), r3 = fmaxf(f23.y, 0.f);
        long t = stok[qr];
        img_write(g_obs, t, head * 64 + d0, 256, r0, r1);
        img_write(g_obs, t, head * 64 + d0 + 2, 256, r2, r3);
    }
}

// ---------------------------------------------------------------------------
extern "C" void kernel_launch(void* const* d_in, const int* in_sizes, int n_in,
                              void* d_out, int out_size)
{
    const float* in[32];
    for (int i = 0; i < n_in && i < 32; i++) in[i] = (const float*)d_in[i];

    int idw0, idw1, iffn0, iffn1, iqkv, idws, iproj, ipos;
    if (in_sizes[4] > 100000) { // reference-signature order
        idw0 = 1;  iffn0 = 4;  iqkv = 10; idws = 13; iproj = 16;
        ipos = 19; idw1 = 20;  iffn1 = 23;
    } else {                    // setup_inputs dict order
        idw0 = 1;  idw1 = 4;   iffn0 = 7;  iffn1 = 13;
        iqkv = 19; idws = 22;  iproj = 25; ipos = 28;
    }

    const float* x     = in[0];
    const float* dw0_w = in[idw0],  * dw0_s = in[idw0 + 1], * dw0_b = in[idw0 + 2];
    const float* dw1_w = in[idw1],  * dw1_s = in[idw1 + 1], * dw1_b = in[idw1 + 2];
    const float* f0w1 = in[iffn0],     * f0s1 = in[iffn0 + 1], * f0b1 = in[iffn0 + 2];
    const float* f0w2 = in[iffn0 + 3], * f0s2 = in[iffn0 + 4], * f0b2 = in[iffn0 + 5];
    const float* f1w1 = in[iffn1],     * f1s1 = in[iffn1 + 1], * f1b1 = in[iffn1 + 2];
    const float* f1w2 = in[iffn1 + 3], * f1s2 = in[iffn1 + 4], * f1b2 = in[iffn1 + 5];
    const float* qkv_w = in[iqkv],  * qkv_s = in[iqkv + 1],  * qkv_b = in[iqkv + 2];
    const float* dws_w = in[idws],  * dws_s = in[idws + 1],  * dws_b = in[idws + 2];
    const float* proj_w = in[iproj], * proj_s = in[iproj + 1], * proj_b = in[iproj + 2];
    const float* pos = in[ipos];

    float* pqkv;
    unsigned char *pxAs, *phs, *pobs, *pxBs, *pwtB;
    cudaGetSymbolAddress((void**)&pqkv, g_qkv);
    cudaGetSymbolAddress((void**)&pxAs, g_xAs);
    cudaGetSymbolAddress((void**)&phs,  g_hs);
    cudaGetSymbolAddress((void**)&pobs, g_obs);
    cudaGetSymbolAddress((void**)&pxBs, g_xBs);
    cudaGetSymbolAddress((void**)&pwtB, g_wtB);

    const int SMEM_GEMM = 81920;
    cudaFuncSetAttribute(mm_gemm, cudaFuncAttributeMaxDynamicSharedMemorySize,
                         SMEM_GEMM);
    const int SMEM_DWS = 784 * 17 * 4;
    cudaFuncSetAttribute(dws_kernel, cudaFuncAttributeMaxDynamicSharedMemorySize,
                         SMEM_DWS);

    const int PGRID = 296;   // 2 CTAs x 148 SMs, persistent

    wconv_all<<<(688128 + 255) / 256, 256>>>(f0w1, f0w2, qkv_w, proj_w, f1w1,
                                             f1w2, pwtB);

    // 1. xA = x + bn(dw3x3(x))  -> image
    dw0_kernel<<<dim3(4, 28, 64), 256>>>(x, dw0_w, dw0_s, dw0_b);

    // 2. ffn0 (h image; then in-place xA image += ffn)
    mm_gemm<<<PGRID, 256, SMEM_GEMM>>>(
        pxAs, pwtB + WB_F0W1, f0s1, f0b1, nullptr, nullptr, phs,
        512, 256, 1, 4, 1568);
    mm_gemm<<<PGRID, 256, SMEM_GEMM>>>(
        phs, pwtB + WB_F0W2, f0s2, f0b2, pxAs, nullptr, pxAs,
        256, 512, 2, 2, 784);

    // 3. attention
    mm_gemm<<<PGRID, 256, SMEM_GEMM>>>(
        pxAs, pwtB + WB_QKV, qkv_s, qkv_b, nullptr, pqkv, nullptr,
        384, 256, 0, 3, 1176);
    dws_kernel<<<dim3(64, 4), 256, SMEM_DWS>>>(dws_w, dws_s, dws_b);
    attn_kernel<<<dim3(16, 4, 64), 128>>>(pos);
    mm_gemm<<<PGRID, 256, SMEM_GEMM>>>(
        pobs, pwtB + WB_PROJ, proj_s, proj_b, pxAs, nullptr, pxAs,
        256, 256, 2, 2, 784);

    // 4. xB image = xA + bn(dw3x3(xA))
    dw1_kernel<<<TOK, 256>>>(dw1_w, dw1_s, dw1_b);

    // 5. ffn1: h image, then final GEMM -> NCHW d_out (epi=3, resid xB image)
    mm_gemm<<<PGRID, 256, SMEM_GEMM>>>(
        pxBs, pwtB + WB_F1W1, f1s1, f1b1, nullptr, nullptr, phs,
        512, 256, 1, 4, 1568);
    mm_gemm<<<PGRID, 256, SMEM_GEMM>>>(
        phs, pwtB + WB_F1W2, f1s2, f1b2, pxBs, (float*)d_out, nullptr,
        256, 512, 3, 2, 784);
}

// round 17
// speedup vs baseline: 1.0821x; 1.0329x over previous
#include <cuda_runtime.h>
#include <cuda_bf16.h>
#include <cstdint>

// ---------------------------------------------------------------------------
// EfficientViT block. HMMA mma.sync bf16 hi/lo-split GEMMs (non-persistent
// grid, bulk-load mainloop, bulk-store epilogue for image outputs), blocked
// bf16 images as the only activation storage, smem-tiled dws, R13 attention,
// per-token dw1.
// ---------------------------------------------------------------------------

#define TOK   50176

__device__ float g_qkv[TOK * 384];
__device__ float g_q2[TOK * 64];

// blocked hi/lo bf16 images: [128 rows x 32 k] tiles, stride 40, hi+lo = 20480B
__device__ __align__(16) unsigned char g_xAs[TOK * 256 * 5];
__device__ __align__(16) unsigned char g_hs [TOK * 512 * 5];
__device__ __align__(16) unsigned char g_obs[TOK * 256 * 5];
__device__ __align__(16) unsigned char g_xBs[TOK * 256 * 5];
__device__ __align__(16) unsigned char g_wtB[3440640];

#define WB_F0W1 0
#define WB_F0W2 655360
#define WB_QKV  1310720
#define WB_PROJ 1802240
#define WB_F1W1 2129920
#define WB_F1W2 2785280

__device__ __forceinline__ uint32_t smem_u32(const void* p) {
    uint32_t a;
    asm("{ .reg .u64 t; cvta.to.shared.u64 t, %1; cvt.u32.u64 %0, t; }"
        : "=r"(a) : "l"(p));
    return a;
}
__device__ __forceinline__ void ldsm4(uint32_t* r, uint32_t addr) {
    asm volatile("ldmatrix.sync.aligned.m8n8.x4.shared.b16 {%0,%1,%2,%3}, [%4];"
        : "=r"(r[0]), "=r"(r[1]), "=r"(r[2]), "=r"(r[3]) : "r"(addr));
}
__device__ __forceinline__ void mma16816(float* c, const uint32_t* a,
                                         const uint32_t* b) {
    asm volatile(
        "mma.sync.aligned.m16n8k16.row.col.f32.bf16.bf16.f32 "
        "{%0,%1,%2,%3}, {%4,%5,%6,%7}, {%8,%9}, {%0,%1,%2,%3};"
        : "+f"(c[0]), "+f"(c[1]), "+f"(c[2]), "+f"(c[3])
        : "r"(a[0]), "r"(a[1]), "r"(a[2]), "r"(a[3]), "r"(b[0]), "r"(b[1]));
}

// packed f32x2 FMA
__device__ __forceinline__ unsigned long long pack2f(float lo, float hi) {
    unsigned long long r;
    asm("mov.b64 %0, {%1,%2};" : "=l"(r) : "f"(lo), "f"(hi));
    return r;
}
__device__ __forceinline__ void ffma2(unsigned long long& d,
                                      unsigned long long a,
                                      unsigned long long b) {
    asm("fma.rn.f32x2 %0, %1, %2, %3;" : "=l"(d) : "l"(a), "l"(b), "l"(d));
}
__device__ __forceinline__ float2 unpack2f(unsigned long long v) {
    float2 f;
    asm("mov.b64 {%0,%1}, %2;" : "=f"(f.x), "=f"(f.y) : "l"(v));
    return f;
}

#define MBARRIER_INIT(mbar_addr, count) \
    asm volatile("mbarrier.init.shared.b64 [%0], %1;" \
        :: "r"((uint32_t)(mbar_addr)), "r"((uint32_t)(count)) : "memory")
#define MBARRIER_EXPECT_TX(mbar_addr, tx_bytes) \
    asm volatile("mbarrier.arrive.expect_tx.shared.b64 _, [%0], %1;" \
        :: "r"((uint32_t)(mbar_addr)), "r"((uint32_t)(tx_bytes)) : "memory")
#define MBARRIER_WAIT_PARITY(mbar_addr, parity) do { \
    uint32_t _mbar = (uint32_t)(mbar_addr); \
    uint32_t _par = (uint32_t)(parity); \
    uint32_t _done; \
    asm volatile( \
        "{\n\t.reg .pred p;\n\t" \
        "mbarrier.try_wait.parity.acquire.cta.shared::cta.b64 p, [%1], %2;\n\t" \
        "selp.b32 %0, 1, 0, p;\n\t}" \
        : "=r"(_done) : "r"(_mbar), "r"(_par) : "memory"); \
    if (!_done) { \
        asm volatile( \
            "{\n\t.reg .pred P1;\n\t" \
            "WAIT_LOOP_%=:\n\t" \
            "mbarrier.try_wait.parity.acquire.cta.shared::cta.b64 P1, [%0], %1, 0x989680;\n\t" \
            "@P1 bra.uni WAIT_DONE_%=;\n\t" \
            "bra.uni WAIT_LOOP_%=;\n\t" \
            "WAIT_DONE_%=:\n\t}" \
            :: "r"(_mbar), "r"(_par) : "memory"); \
    } \
} while (0)

__device__ __forceinline__ void bulkcp(uint32_t dst, const void* src,
                                       uint32_t mbar) {
    asm volatile(
        "cp.async.bulk.shared::cta.global.mbarrier::complete_tx::bytes "
        "[%0], [%1], %2, [%3];"
        :: "r"(dst), "l"(src), "r"(20480u), "r"(mbar) : "memory");
}

// blocked-image byte offset of (row, col) hi element; lo at +10240
__device__ __forceinline__ long img_off(long row, int col, int Kd) {
    return ((row >> 7) * (Kd >> 5) + (col >> 5)) * 20480L +
           (row & 127) * 80 + (col & 31) * 2;
}
__device__ __forceinline__ float img_read(const unsigned char* img, long row,
                                          int col, int Kd) {
    long off = img_off(row, col, Kd);
    return __bfloat162float(*(const __nv_bfloat16*)(img + off)) +
           __bfloat162float(*(const __nv_bfloat16*)(img + off + 10240));
}

#define TS 40
__device__ __forceinline__ uint32_t a_addr(uint32_t base, int m, int k, int lane) {
    int g = lane >> 3, r = lane & 7;
    return base + ((m + ((g & 1) << 3) + r) * TS + k + ((g >> 1) << 3)) * 2;
}
__device__ __forceinline__ uint32_t b_addr(uint32_t base, int n, int k, int lane) {
    int g = lane >> 3, r = lane & 7;
    return base + ((n + ((g >> 1) << 3) + r) * TS + k + ((g & 1) << 3)) * 2;
}

__device__ __forceinline__ void split_bf16(float v, __nv_bfloat16& h,
                                           __nv_bfloat16& l) {
    h = __float2bfloat16(v);
    l = __float2bfloat16(v - __bfloat162float(h));
}
__device__ __forceinline__ void img_write(unsigned char* img, long row, int col,
                                          int Kd, float v0, float v1) {
    __nv_bfloat16 h0, l0, h1, l1;
    split_bf16(v0, h0, l0);
    split_bf16(v1, h1, l1);
    long off = img_off(row, col, Kd);
    __nv_bfloat162 hv, lv;
    hv.x = h0; hv.y = h1;
    lv.x = l0; lv.y = l1;
    *(__nv_bfloat162*)(img + off) = hv;
    *(__nv_bfloat162*)(img + off + 10240) = lv;
}

// ---------------------------------------------------------------------------
// All-weights split into blocked images, one launch
// ---------------------------------------------------------------------------
__global__ void wconv_all(const float* __restrict__ w0, const float* __restrict__ w1,
                          const float* __restrict__ w2, const float* __restrict__ w3,
                          const float* __restrict__ w4, const float* __restrict__ w5,
                          unsigned char* __restrict__ dst) {
    long i = (long)blockIdx.x * 256 + threadIdx.x;
    if (i >= 688128) return;
    const long cum[7] = {0, 131072, 262144, 360448, 425984, 557056, 688128};
    const long ob[6] = {WB_F0W1, WB_F0W2, WB_QKV, WB_PROJ, WB_F1W1, WB_F1W2};
    const int Ks[6] = {256, 512, 256, 256, 256, 512};
    const float* srcs[6] = {w0, w1, w2, w3, w4, w5};
    int s = 0;
    while (i >= cum[s + 1]) s++;
    long j = i - cum[s];
    int K = Ks[s];
    long n = j / K;
    int k = (int)(j % K);
    __nv_bfloat16 h, l;
    split_bf16(srcs[s][j], h, l);
    long off = ob[s] + img_off(n, k, K);
    *(__nv_bfloat16*)(dst + off) = h;
    *(__nv_bfloat16*)(dst + off + 10240) = l;
}

// ---------------------------------------------------------------------------
// HMMA GEMM (one tile per CTA). epi: 0 fp32 out ; 1 relu->img ;
// 2 resid(img)+ ->img ; 3 resid(img)+ -> NCHW fp32 transpose out
// epi 1/2: smem-staged output + cp.async.bulk S2G (contiguous 81920B)
// ---------------------------------------------------------------------------
__global__ void __launch_bounds__(256, 2) mm_gemm(
    const unsigned char* __restrict__ Aimg, const unsigned char* __restrict__ Bimg,
    const float* __restrict__ sc, const float* __restrict__ bi,
    const unsigned char* __restrict__ residImg, float* __restrict__ Cf,
    unsigned char* __restrict__ Chl,
    int N, int K, int epi)
{
    extern __shared__ __align__(128) unsigned char dsm[];
    __shared__ __align__(8) unsigned long long mbars[2];
    int tid = threadIdx.x, lane = tid & 31, wid = tid >> 5;
    int wm = (wid & 1) << 6, wn = (wid >> 1) << 5;
    long bm = (long)blockIdx.y << 7;
    int bn = blockIdx.x << 7;
    int KT = K >> 5;

    float acc[4][4][4] = {};
    uint32_t sbase = smem_u32(dsm);
    uint32_t mb = smem_u32(mbars);

    if (tid == 0) {
        MBARRIER_INIT(mb, 1);
        MBARRIER_INIT(mb + 8, 1);
    }
    __syncthreads();

    const unsigned char* Ab = Aimg + (long)blockIdx.y * KT * 20480;
    const unsigned char* Bb = Bimg + (long)blockIdx.x * KT * 20480;

    if (tid == 0) {
        MBARRIER_EXPECT_TX(mb, 40960);
        bulkcp(sbase, Ab, mb);
        bulkcp(sbase + 20480, Bb, mb);
        if (KT > 1) {
            MBARRIER_EXPECT_TX(mb + 8, 40960);
            bulkcp(sbase + 40960, Ab + 20480, mb + 8);
            bulkcp(sbase + 61440, Bb + 20480, mb + 8);
        }
    }

    for (int t = 0; t < KT; t++) {
        MBARRIER_WAIT_PARITY(mb + (t & 1) * 8, (t >> 1) & 1);
        uint32_t sAh = sbase + (t & 1) * 40960;
        uint32_t sAl = sAh + 10240;
        uint32_t sBh = sAh + 20480;
        uint32_t sBl = sAh + 30720;
#pragma unroll
        for (int kk = 0; kk < 32; kk += 16) {
            uint32_t ah[4][4], al[4][4], bh[2][4], bl[2][4];
#pragma unroll
            for (int mt = 0; mt < 4; mt++)
                ldsm4(ah[mt], a_addr(sAh, wm + mt * 16, kk, lane));
#pragma unroll
            for (int h = 0; h < 2; h++)
                ldsm4(bh[h], b_addr(sBh, wn + h * 16, kk, lane));
#pragma unroll
            for (int mt = 0; mt < 4; mt++)
#pragma unroll
                for (int nt = 0; nt < 4; nt++)
                    mma16816(acc[mt][nt], ah[mt], &bh[nt >> 1][(nt & 1) * 2]);
#pragma unroll
            for (int h = 0; h < 2; h++)
                ldsm4(bl[h], b_addr(sBl, wn + h * 16, kk, lane));
#pragma unroll
            for (int mt = 0; mt < 4; mt++)
#pragma unroll
                for (int nt = 0; nt < 4; nt++)
                    mma16816(acc[mt][nt], ah[mt], &bl[nt >> 1][(nt & 1) * 2]);
#pragma unroll
            for (int mt = 0; mt < 4; mt++)
                ldsm4(al[mt], a_addr(sAl, wm + mt * 16, kk, lane));
#pragma unroll
            for (int mt = 0; mt < 4; mt++)
#pragma unroll
                for (int nt = 0; nt < 4; nt++)
                    mma16816(acc[mt][nt], al[mt], &bh[nt >> 1][(nt & 1) * 2]);
        }
        __syncthreads();
        if (tid == 0 && t + 2 < KT) {
            uint32_t b8 = mb + (t & 1) * 8;
            uint32_t sb = sbase + (t & 1) * 40960;
            MBARRIER_EXPECT_TX(b8, 40960);
            bulkcp(sb, Ab + (long)(t + 2) * 20480, b8);
            bulkcp(sb + 20480, Bb + (long)(t + 2) * 20480, b8);
        }
    }

    int q = lane >> 2, tq = lane & 3;

    if (epi == 3) {
        float* tile = (float*)dsm;   // [128][129]
#pragma unroll
        for (int nt = 0; nt < 4; nt++) {
            int nl = wn + nt * 8 + tq * 2;
            int n = bn + nl;
            float2 s2 = *(const float2*)(sc + n);
            float2 b2 = *(const float2*)(bi + n);
#pragma unroll
            for (int mt = 0; mt < 4; mt++) {
#pragma unroll
                for (int half = 0; half < 2; half++) {
                    int row = wm + mt * 16 + q + half * 8;
                    long m = bm + row;
                    long off = img_off(m, n, N);
                    __nv_bfloat162 rh = *(const __nv_bfloat162*)(residImg + off);
                    __nv_bfloat162 rl = *(const __nv_bfloat162*)(residImg + off + 10240);
                    tile[row * 129 + nl]     = acc[mt][nt][half * 2 + 0] * s2.x + b2.x +
                        __bfloat162float(rh.x) + __bfloat162float(rl.x);
                    tile[row * 129 + nl + 1] = acc[mt][nt][half * 2 + 1] * s2.y + b2.y +
                        __bfloat162float(rh.y) + __bfloat162float(rl.y);
                }
            }
        }
        __syncthreads();
#pragma unroll
        for (int ci = 0; ci < 16; ci++) {
            int c = wid * 16 + ci;
#pragma unroll
            for (int rc = 0; rc < 4; rc++) {
                int row = rc * 32 + lane;
                long tk = bm + row;
                int b = (int)(tk / 784), tr = (int)(tk % 784);
                Cf[((long)(b * 256 + bn + c)) * 784 + tr] = tile[row * 129 + c];
            }
        }
        return;
    }

    if (epi == 0) {
#pragma unroll
        for (int nt = 0; nt < 4; nt++) {
            int n = bn + wn + nt * 8 + tq * 2;
            float2 s2 = *(const float2*)(sc + n);
            float2 b2 = *(const float2*)(bi + n);
#pragma unroll
            for (int mt = 0; mt < 4; mt++) {
#pragma unroll
                for (int half = 0; half < 2; half++) {
                    long m = bm + wm + mt * 16 + q + half * 8;
                    float2 o;
                    o.x = acc[mt][nt][half * 2 + 0] * s2.x + b2.x;
                    o.y = acc[mt][nt][half * 2 + 1] * s2.y + b2.y;
                    *(float2*)(Cf + m * N + n) = o;
                }
            }
        }
        return;
    }

    // epi 1/2: stage blocked-image output in smem, bulk-store 81920 B
#pragma unroll
    for (int nt = 0; nt < 4; nt++) {
        int nl = wn + nt * 8 + tq * 2;
        int n = bn + nl;
        float2 s2 = *(const float2*)(sc + n);
        float2 b2 = *(const float2*)(bi + n);
#pragma unroll
        for (int mt = 0; mt < 4; mt++) {
#pragma unroll
            for (int half = 0; half < 2; half++) {
                int row = wm + mt * 16 + q + half * 8;
                long m = bm + row;
                float v0 = acc[mt][nt][half * 2 + 0] * s2.x + b2.x;
                float v1 = acc[mt][nt][half * 2 + 1] * s2.y + b2.y;
                if (epi == 1) {
                    v0 = fmaxf(v0, 0.f);
                    v1 = fmaxf(v1, 0.f);
                } else {
                    long off = img_off(m, n, N);
                    __nv_bfloat162 rh = *(const __nv_bfloat162*)(residImg + off);
                    __nv_bfloat162 rl = *(const __nv_bfloat162*)(residImg + off + 10240);
                    v0 += __bfloat162float(rh.x) + __bfloat162float(rl.x);
                    v1 += __bfloat162float(rh.y) + __bfloat162float(rl.y);
                }
                __nv_bfloat16 h0, l0, h1, l1;
                split_bf16(v0, h0, l0);
                split_bf16(v1, h1, l1);
                __nv_bfloat162 hv, lv;
                hv.x = h0; hv.y = h1;
                lv.x = l0; lv.y = l1;
                uint32_t so = (uint32_t)((nl >> 5) * 20480 + row * 80 +
                                         (nl & 31) * 2);
                *(__nv_bfloat162*)(dsm + so) = hv;
                *(__nv_bfloat162*)(dsm + so + 10240) = lv;
            }
        }
    }
    __syncthreads();
    if (tid == 0) {
        asm volatile("fence.proxy.async.shared::cta;" ::: "memory");
        unsigned char* gdst =
            Chl + ((long)blockIdx.y * (N >> 5) + ((long)blockIdx.x << 2)) * 20480;
        asm volatile(
            "cp.async.bulk.global.shared::cta.bulk_group [%0], [%1], %2;"
            :: "l"(gdst), "r"(sbase), "r"(81920u) : "memory");
        asm volatile("cp.async.bulk.commit_group;" ::: "memory");
        asm volatile("cp.async.bulk.wait_group 0;" ::: "memory");
    }
}

// ---------------------------------------------------------------------------
// dw0: NCHW input -> blocked image only, xA = x + bn(dw3x3(x))
// ---------------------------------------------------------------------------
__global__ void __launch_bounds__(256) dw0_kernel(
    const float* __restrict__ x, const float* __restrict__ w,
    const float* __restrict__ s, const float* __restrict__ bb)
{
    __shared__ float sx[3][64][29];
    __shared__ float wsm[64][9];
    __shared__ float ssm[64], bsm[64];
    int c0 = blockIdx.x * 64;
    int h = blockIdx.y;
    int b = blockIdx.z;
    int tid = threadIdx.x;

    for (int i = tid; i < 64 * 9; i += 256) {
        int c = i / 9, k = i % 9;
        wsm[c][k] = w[(c0 + c) * 9 + k];
    }
    if (tid < 64) { ssm[tid] = s[c0 + tid]; bsm[tid] = bb[c0 + tid]; }

    for (int i = tid; i < 3 * 64 * 28; i += 256) {
        int row = i / 1792;
        int rem = i % 1792;
        int c = rem / 28, ww = rem % 28;
        int hh = h - 1 + row;
        float v = 0.f;
        if (hh >= 0 && hh < 28)
            v = x[(((long)(b * 256 + c0 + c)) * 28 + hh) * 28 + ww];
        sx[row][c][ww] = v;
    }
    __syncthreads();

    for (int i = tid; i < 64 * 28; i += 256) {
        int cl = i & 63, ww = i >> 6;
        float acc = 0.f;
#pragma unroll
        for (int dy = 0; dy < 3; dy++)
#pragma unroll
            for (int dx = 0; dx < 3; dx++) {
                int w2 = ww + dx - 1;
                if (w2 >= 0 && w2 < 28)
                    acc += wsm[cl][dy * 3 + dx] * sx[dy][cl][w2];
            }
        long t = (long)(b * 28 + h) * 28 + ww;
        float v = sx[1][cl][ww] + ssm[cl] * acc + bsm[cl];
        __nv_bfloat16 hh2, ll2;
        split_bf16(v, hh2, ll2);
        long off = img_off(t, c0 + cl, 256);
        *(__nv_bfloat16*)(g_xAs + off) = hh2;
        *(__nv_bfloat16*)(g_xAs + off + 10240) = ll2;
    }
}

// ---------------------------------------------------------------------------
// dw1 (R13 form): per-token block, channel-major coalesced image reads
// ---------------------------------------------------------------------------
__global__ void __launch_bounds__(256) dw1_kernel(
    const float* __restrict__ w, const float* __restrict__ s,
    const float* __restrict__ bb)
{
    int t = blockIdx.x;
    int c = threadIdx.x;
    int b = t / 784, rem = t % 784, h = rem / 28, ww = rem % 28;
    float wr[9];
#pragma unroll
    for (int k = 0; k < 9; k++) wr[k] = w[c * 9 + k];
    float acc = 0.f, center = 0.f;
#pragma unroll
    for (int dy = 0; dy < 3; dy++) {
        int h2 = h + dy - 1;
        if (h2 < 0 || h2 >= 28) continue;
#pragma unroll
        for (int dx = 0; dx < 3; dx++) {
            int w2 = ww + dx - 1;
            if (w2 < 0 || w2 >= 28) continue;
            float v = img_read(g_xAs, (long)(b * 784 + h2 * 28 + w2), c, 256);
            acc += wr[dy * 3 + dx] * v;
            if (dy == 1 && dx == 1) center = v;
        }
    }
    float out = center + s[c] * acc + bb[c];
    __nv_bfloat16 hh, ll;
    split_bf16(out, hh, ll);
    long off = img_off(t, c, 256);
    *(__nv_bfloat16*)(g_xBs + off) = hh;
    *(__nv_bfloat16*)(g_xBs + off + 10240) = ll;
}

// ---------------------------------------------------------------------------
// dws: 5x5 depthwise conv, smem-tiled per (batch, head). grid (64, 4), 256 thr
// ---------------------------------------------------------------------------
__global__ void __launch_bounds__(256) dws_kernel(
    const float* __restrict__ w, const float* __restrict__ s,
    const float* __restrict__ bb)
{
    extern __shared__ float sx[];   // [784][17]
    int b = blockIdx.x, head = blockIdx.y;
    int tid = threadIdx.x;
    int kc = tid & 15, tg = tid >> 4;

    for (int i = tid; i < 784 * 16; i += 256) {
        int t = i >> 4, k2 = i & 15;
        sx[t * 17 + k2] = g_qkv[((long)(b * 784 + t)) * 384 + head * 96 + k2];
    }
    __syncthreads();

    int ch = head * 16 + kc;
    float wr[25];
#pragma unroll
    for (int k = 0; k < 25; k++) wr[k] = w[ch * 25 + k];
    float sv = s[ch], bv = bb[ch];

    for (int j = 0; j < 49; j++) {
        int t = tg + (j << 4);
        int h = t / 28, ww = t % 28;
        float acc = 0.f;
#pragma unroll
        for (int dy = 0; dy < 5; dy++) {
            int h2 = h + dy - 2;
            if (h2 < 0 || h2 >= 28) continue;
#pragma unroll
            for (int dx = 0; dx < 5; dx++) {
                int w2 = ww + dx - 2;
                if (w2 < 0 || w2 >= 28) continue;
                acc += wr[dy * 5 + dx] * sx[(h2 * 28 + w2) * 17 + kc];
            }
        }
        g_q2[((long)(b * 784 + t)) * 64 + ch] = sv * acc + bv;
    }
}

// ---------------------------------------------------------------------------
// per-window attention (7x7 = 49 tokens), f32x2 math (R13 form)
// ---------------------------------------------------------------------------
__global__ void __launch_bounds__(128) attn_kernel(const float* __restrict__ pos)
{
    int wi = blockIdx.x >> 2, wj = blockIdx.x & 3;
    int head = blockIdx.y, b = blockIdx.z;
    int tid = threadIdx.x;

    __shared__ __align__(8) float sq[49 * 18];
    __shared__ __align__(8) float sk[49 * 18];
    __shared__ __align__(16) float sv[49 * 64];
    __shared__ __align__(8) float ss[49 * 50];
    __shared__ int stok[49];

    if (tid < 49)
        stok[tid] = b * 784 + (wi * 7 + tid / 7) * 28 + wj * 7 + (tid % 7);
    __syncthreads();

    for (int i = tid; i < 49 * 16; i += 128) {
        int r = i >> 4, c = i & 15;
        long t = stok[r];
        sq[r * 18 + c] = g_q2[t * 64 + head * 16 + c];
        sk[r * 18 + c] = g_qkv[t * 384 + head * 96 + 16 + c];
    }
    for (int i = tid; i < 49 * 64; i += 128) {
        int r = i >> 6, c = i & 63;
        sv[i] = g_qkv[(long)stok[r] * 384 + head * 96 + 32 + c];
    }
    __syncthreads();

    const float* pe = pos + head * 49 * 49;
    for (int i = tid; i < 49 * 49; i += 128) {
        int qr = i / 49, kr = i % 49;
        unsigned long long d2 = pack2f(0.f, 0.f);
#pragma unroll
        for (int cc = 0; cc < 8; cc++) {
            unsigned long long a2 = *(const unsigned long long*)&sq[qr * 18 + cc * 2];
            unsigned long long b2 = *(const unsigned long long*)&sk[kr * 18 + cc * 2];
            ffma2(d2, a2, b2);
        }
        float2 f = unpack2f(d2);
        ss[qr * 50 + kr] = (f.x + f.y) * 0.25f + pe[i];
    }
    __syncthreads();

    {   // softmax, 2 threads per row + shfl combine
        int r = tid >> 1, hf = tid & 1;
        bool act = r < 49;
        float* row = ss + (act ? r : 0) * 50;
        int k0 = hf ? 25 : 0, cnt = hf ? 24 : 25;
        float mx = -1e30f;
        for (int k = 0; k < cnt; k++) mx = fmaxf(mx, row[k0 + k]);
        mx = fmaxf(mx, __shfl_xor_sync(0xffffffffu, mx, 1));
        float ev[25];
        float sum = 0.f;
        for (int k = 0; k < cnt; k++) {
            ev[k] = __expf(row[k0 + k] - mx);
            sum += ev[k];
        }
        sum += __shfl_xor_sync(0xffffffffu, sum, 1);
        float inv = 1.f / sum;
        if (act)
            for (int k = 0; k < cnt; k++) row[k0 + k] = ev[k] * inv;
    }
    __syncthreads();

    for (int i = tid; i < 49 * 16; i += 128) {
        int qr = i >> 4, d0 = (i & 15) << 2;
        unsigned long long a01 = pack2f(0.f, 0.f), a23 = pack2f(0.f, 0.f);
        for (int k = 0; k < 49; k++) {
            float p = ss[qr * 50 + k];
            unsigned long long p2 = pack2f(p, p);
            ffma2(a01, p2, *(const unsigned long long*)&sv[k * 64 + d0]);
            ffma2(a23, p2, *(const unsigned long long*)&sv[k * 64 + d0 + 2]);
        }
        float2 f01 = unpack2f(a01), f23 = unpack2f(a23);
        float r0 = fmaxf(f01.x, 0.f), r1 = fmaxf(f01.y, 0.f);
        float r2 = fmaxf(f23.x, 0.f), r3 = fmaxf(f23.y, 0.f);
        long t = stok[qr];
        img_write(g_obs, t, head * 64 + d0, 256, r0, r1);
        img_write(g_obs, t, head * 64 + d0 + 2, 256, r2, r3);
    }
}

// ---------------------------------------------------------------------------
extern "C" void kernel_launch(void* const* d_in, const int* in_sizes, int n_in,
                              void* d_out, int out_size)
{
    const float* in[32];
    for (int i = 0; i < n_in && i < 32; i++) in[i] = (const float*)d_in[i];

    int idw0, idw1, iffn0, iffn1, iqkv, idws, iproj, ipos;
    if (in_sizes[4] > 100000) { // reference-signature order
        idw0 = 1;  iffn0 = 4;  iqkv = 10; idws = 13; iproj = 16;
        ipos = 19; idw1 = 20;  iffn1 = 23;
    } else {                    // setup_inputs dict order
        idw0 = 1;  idw1 = 4;   iffn0 = 7;  iffn1 = 13;
        iqkv = 19; idws = 22;  iproj = 25; ipos = 28;
    }

    const float* x     = in[0];
    const float* dw0_w = in[idw0],  * dw0_s = in[idw0 + 1], * dw0_b = in[idw0 + 2];
    const float* dw1_w = in[idw1],  * dw1_s = in[idw1 + 1], * dw1_b = in[idw1 + 2];
    const float* f0w1 = in[iffn0],     * f0s1 = in[iffn0 + 1], * f0b1 = in[iffn0 + 2];
    const float* f0w2 = in[iffn0 + 3], * f0s2 = in[iffn0 + 4], * f0b2 = in[iffn0 + 5];
    const float* f1w1 = in[iffn1],     * f1s1 = in[iffn1 + 1], * f1b1 = in[iffn1 + 2];
    const float* f1w2 = in[iffn1 + 3], * f1s2 = in[iffn1 + 4], * f1b2 = in[iffn1 + 5];
    const float* qkv_w = in[iqkv],  * qkv_s = in[iqkv + 1],  * qkv_b = in[iqkv + 2];
    const float* dws_w = in[idws],  * dws_s = in[idws + 1],  * dws_b = in[idws + 2];
    const float* proj_w = in[iproj], * proj_s = in[iproj + 1], * proj_b = in[iproj + 2];
    const float* pos = in[ipos];

    float* pqkv;
    unsigned char *pxAs, *phs, *pobs, *pxBs, *pwtB;
    cudaGetSymbolAddress((void**)&pqkv, g_qkv);
    cudaGetSymbolAddress((void**)&pxAs, g_xAs);
    cudaGetSymbolAddress((void**)&phs,  g_hs);
    cudaGetSymbolAddress((void**)&pobs, g_obs);
    cudaGetSymbolAddress((void**)&pxBs, g_xBs);
    cudaGetSymbolAddress((void**)&pwtB, g_wtB);

    const int SMEM_GEMM = 81920;
    cudaFuncSetAttribute(mm_gemm, cudaFuncAttributeMaxDynamicSharedMemorySize,
                         SMEM_GEMM);
    const int SMEM_DWS = 784 * 17 * 4;
    cudaFuncSetAttribute(dws_kernel, cudaFuncAttributeMaxDynamicSharedMemorySize,
                         SMEM_DWS);

    wconv_all<<<(688128 + 255) / 256, 256>>>(f0w1, f0w2, qkv_w, proj_w, f1w1,
                                             f1w2, pwtB);

    // 1. xA = x + bn(dw3x3(x))  -> image
    dw0_kernel<<<dim3(4, 28, 64), 256>>>(x, dw0_w, dw0_s, dw0_b);

    // 2. ffn0 (h image; then in-place xA image += ffn)
    mm_gemm<<<dim3(4, 392), 256, SMEM_GEMM>>>(
        pxAs, pwtB + WB_F0W1, f0s1, f0b1, nullptr, nullptr, phs, 512, 256, 1);
    mm_gemm<<<dim3(2, 392), 256, SMEM_GEMM>>>(
        phs, pwtB + WB_F0W2, f0s2, f0b2, pxAs, nullptr, pxAs, 256, 512, 2);

    // 3. attention
    mm_gemm<<<dim3(3, 392), 256, SMEM_GEMM>>>(
        pxAs, pwtB + WB_QKV, qkv_s, qkv_b, nullptr, pqkv, nullptr, 384, 256, 0);
    dws_kernel<<<dim3(64, 4), 256, SMEM_DWS>>>(dws_w, dws_s, dws_b);
    attn_kernel<<<dim3(16, 4, 64), 128>>>(pos);
    mm_gemm<<<dim3(2, 392), 256, SMEM_GEMM>>>(
        pobs, pwtB + WB_PROJ, proj_s, proj_b, pxAs, nullptr, pxAs, 256, 256, 2);

    // 4. xB image = xA + bn(dw3x3(xA))
    dw1_kernel<<<TOK, 256>>>(dw1_w, dw1_s, dw1_b);

    // 5. ffn1: h image, then final GEMM -> NCHW d_out (epi=3, resid xB image)
    mm_gemm<<<dim3(4, 392), 256, SMEM_GEMM>>>(
        pxBs, pwtB + WB_F1W1, f1s1, f1b1, nullptr, nullptr, phs, 512, 256, 1);
    mm_gemm<<<dim3(2, 392), 256, SMEM_GEMM>>>(
        phs, pwtB + WB_F1W2, f1s2, f1b2, pxBs, (float*)d_out, nullptr,
        256, 512, 3);
}